// round 8
// baseline (speedup 1.0000x reference)
#include <cuda_runtime.h>
#include <cuda_fp16.h>
#include <math.h>
#include <stdint.h>

// ---------------- problem constants ----------------
#define BB        2
#define SS        4096
#define HH        2048
#define NHEADS    16
#define HDIM      128
#define KSEL      128
#define NROWS     (BB*SS)            // 8192
#define NBH       (BB*NHEADS)        // 32
#define ROWHID    ((long)NROWS*HH)   // 16777216
#define WN        ((long)HH*HH)      // 4194304
#define SELN      (NBH*KSEL*HDIM)    // 524288

// ---------------- scratch (device globals; no allocs allowed) ----------------
__device__ float  gTmp[ROWHID];          // hidden, then attn scores (fp32)
__device__ float  gScores[NBH*SS];
__device__ int    gIdx[NBH*KSEL];
__device__ __half gXhi[ROWHID];
__device__ __half gXlo[ROWHID];
__device__ __half gQhi[ROWHID];
__device__ __half gKhi[ROWHID];
__device__ __half gKlo[ROWHID];
__device__ __half gVhi[ROWHID];
__device__ __half gVlo[ROWHID];
__device__ __half gPhi[ROWHID];
__device__ __half gOhi[ROWHID];
__device__ __half gWhi[WN];
__device__ __half gWlo[WN];
__device__ __half gKselh[SELN];
__device__ __half gKsell[SELN];
__device__ __half gVselTh[SELN];
__device__ __half gVselTl[SELN];

// =================== helpers ===================
__device__ __forceinline__ uint32_t smem_u32(const void* p) {
    uint32_t a;
    asm("{ .reg .u64 t; cvta.to.shared.u64 t, %1; cvt.u32.u64 %0, t; }" : "=r"(a) : "l"(p));
    return a;
}
__device__ __forceinline__ void cp16(uint32_t dst, const void* src) {
    asm volatile("cp.async.cg.shared.global [%0], [%1], 16;" :: "r"(dst), "l"(src));
}
__device__ __forceinline__ void cp_commit() {
    asm volatile("cp.async.commit_group;" ::: "memory");
}
template<int N>
__device__ __forceinline__ void cp_wait() {
    asm volatile("cp.async.wait_group %0;" :: "n"(N) : "memory");
}
__device__ __forceinline__ void mma16816(float* c, const uint32_t* a, uint32_t b0, uint32_t b1) {
    asm volatile(
        "mma.sync.aligned.m16n8k16.row.col.f32.f16.f16.f32 "
        "{%0,%1,%2,%3}, {%4,%5,%6,%7}, {%8,%9}, {%0,%1,%2,%3};"
        : "+f"(c[0]), "+f"(c[1]), "+f"(c[2]), "+f"(c[3])
        : "r"(a[0]), "r"(a[1]), "r"(a[2]), "r"(a[3]), "r"(b0), "r"(b1));
}

// =================== splits ===================
__global__ void split2h(const float* __restrict__ s, __half* __restrict__ hi,
                        __half* __restrict__ lo, long n)
{
    long i = (long)blockIdx.x * blockDim.x + threadIdx.x;
    if (i >= n) return;
    float x = s[i];
    __half h = __float2half_rn(x);
    hi[i] = h;
    lo[i] = __float2half_rn((x - __half2float(h)) * 64.0f);
}
__global__ void split1h(const float* __restrict__ s, __half* __restrict__ hi, long n)
{
    long i = (long)blockIdx.x * blockDim.x + threadIdx.x;
    if (i >= n) return;
    hi[i] = __float2half_rn(s[i]);
}

#define SKW 40
#define PLANE_B (128 * SKW * 2)      // 10240 bytes
#define PLANE_BW (256 * SKW * 2)     // 20480 bytes (wide B tile)

// =================== HMMA split GEMM (128x128 tile): C = alpha * A * B^T ====
// NPROD==3: C ~= Ahi*Bhi + (Ahi*Blo + Alo*Bhi)/64   (planes: Ahi,Bhi,Blo,Alo)
// NPROD==2: C ~= Ahi*Bhi + (Ahi*Blo)/64             (planes: Ahi,Bhi,Blo)
// EMIT: 0 = fp32 to Cf; 1 = fp16 hi+lo planes (Chi,Clo); 2 = fp16 hi only.
// Batched via blockIdx.z (zb=z>>4, zh=z&15).
template<int NPROD, int EMIT>
__global__ __launch_bounds__(256, 1) void hgemm(
    const __half* __restrict__ Ahi, const __half* __restrict__ Alo,
    const __half* __restrict__ Bhi, const __half* __restrict__ Blo,
    float* __restrict__ Cf, __half* __restrict__ Chi, __half* __restrict__ Clo,
    int lda, int ldb, int ldc,
    long strAb, long strAh, long strBb, long strBh, long strCb, long strCh,
    int Kd, float alpha)
{
    constexpr int NPL = (NPROD == 3) ? 4 : 3;
    constexpr int STG = NPL * PLANE_B;
    extern __shared__ char smem[];
    const uint32_t smb = smem_u32(smem);
    const int tid  = threadIdx.x;
    const int wid  = tid >> 5;
    const int lane = tid & 31;
    const int wm   = wid & 1;
    const int wn   = wid >> 1;
    const int qrow = lane >> 2;
    const int qk   = (lane & 3) * 2;

    const int z = blockIdx.z, zb = z >> 4, zh = z & 15;
    const long m0 = (long)blockIdx.y * 128;
    const long n0 = (long)blockIdx.x * 128;

    const __half* pg[4];
    int pld[4];
    pg[0] = Ahi + zb * strAb + zh * strAh + m0 * lda;  pld[0] = lda;
    pg[1] = Bhi + zb * strBb + zh * strBh + n0 * ldb;  pld[1] = ldb;
    pg[2] = Blo + zb * strBb + zh * strBh + n0 * ldb;  pld[2] = ldb;
    pg[3] = (NPROD == 3) ? (Alo + zb * strAb + zh * strAh + m0 * lda) : pg[0];
    pld[3] = lda;

    const int r0 = tid >> 2, s0 = tid & 3;
    const int r1 = r0 + 64;

    float acc[4][4][4], axx[4][4][4];
#pragma unroll
    for (int i = 0; i < 4; i++)
#pragma unroll
        for (int j = 0; j < 4; j++)
#pragma unroll
            for (int r = 0; r < 4; r++) { acc[i][j][r] = 0.f; axx[i][j][r] = 0.f; }

    const int NC = Kd / 32;

#pragma unroll
    for (int p = 0; p < NPL; p++) {
        cp16(smb + p * PLANE_B + r0 * (SKW * 2) + s0 * 16, pg[p] + (long)r0 * pld[p] + s0 * 8);
        cp16(smb + p * PLANE_B + r1 * (SKW * 2) + s0 * 16, pg[p] + (long)r1 * pld[p] + s0 * 8);
    }
    cp_commit();

    for (int ch = 0; ch < NC; ch++) {
        const int st = ch & 1;
        if (ch + 1 < NC) {
            const int k0 = (ch + 1) * 32;
            const uint32_t sb = smb + (st ^ 1) * STG;
#pragma unroll
            for (int p = 0; p < NPL; p++) {
                cp16(sb + p * PLANE_B + r0 * (SKW * 2) + s0 * 16, pg[p] + (long)r0 * pld[p] + k0 + s0 * 8);
                cp16(sb + p * PLANE_B + r1 * (SKW * 2) + s0 * 16, pg[p] + (long)r1 * pld[p] + k0 + s0 * 8);
            }
            cp_commit();
            cp_wait<1>();
        } else {
            cp_wait<0>();
        }
        __syncthreads();

        const uint32_t* pAh = (const uint32_t*)(smem + st * STG + 0 * PLANE_B);
        const uint32_t* pBh = (const uint32_t*)(smem + st * STG + 1 * PLANE_B);
        const uint32_t* pBl = (const uint32_t*)(smem + st * STG + 2 * PLANE_B);
        const uint32_t* pAl = (const uint32_t*)(smem + st * STG + 3 * PLANE_B);

#pragma unroll
        for (int ks = 0; ks < 2; ks++) {
            const int kb = ks * 16;
            uint32_t af[4][4], bf[4][2];
#pragma unroll
            for (int mt = 0; mt < 4; mt++) {
                const int mr = wm * 64 + mt * 16 + qrow;
                af[mt][0] = pAh[(mr * SKW + kb + qk) >> 1];
                af[mt][1] = pAh[((mr + 8) * SKW + kb + qk) >> 1];
                af[mt][2] = pAh[(mr * SKW + kb + qk + 8) >> 1];
                af[mt][3] = pAh[((mr + 8) * SKW + kb + qk + 8) >> 1];
            }
#pragma unroll
            for (int nt = 0; nt < 4; nt++) {
                const int nr = wn * 32 + nt * 8 + qrow;
                bf[nt][0] = pBh[(nr * SKW + kb + qk) >> 1];
                bf[nt][1] = pBh[(nr * SKW + kb + qk + 8) >> 1];
            }
#pragma unroll
            for (int mt = 0; mt < 4; mt++)
#pragma unroll
                for (int nt = 0; nt < 4; nt++)
                    mma16816(acc[mt][nt], af[mt], bf[nt][0], bf[nt][1]);
            {
                uint32_t bl[4][2];
#pragma unroll
                for (int nt = 0; nt < 4; nt++) {
                    const int nr = wn * 32 + nt * 8 + qrow;
                    bl[nt][0] = pBl[(nr * SKW + kb + qk) >> 1];
                    bl[nt][1] = pBl[(nr * SKW + kb + qk + 8) >> 1];
                }
#pragma unroll
                for (int mt = 0; mt < 4; mt++)
#pragma unroll
                    for (int nt = 0; nt < 4; nt++)
                        mma16816(axx[mt][nt], af[mt], bl[nt][0], bl[nt][1]);
            }
            if (NPROD == 3) {
#pragma unroll
                for (int mt = 0; mt < 4; mt++) {
                    const int mr = wm * 64 + mt * 16 + qrow;
                    af[mt][0] = pAl[(mr * SKW + kb + qk) >> 1];
                    af[mt][1] = pAl[((mr + 8) * SKW + kb + qk) >> 1];
                    af[mt][2] = pAl[(mr * SKW + kb + qk + 8) >> 1];
                    af[mt][3] = pAl[((mr + 8) * SKW + kb + qk + 8) >> 1];
                }
#pragma unroll
                for (int mt = 0; mt < 4; mt++)
#pragma unroll
                    for (int nt = 0; nt < 4; nt++)
                        mma16816(axx[mt][nt], af[mt], bf[nt][0], bf[nt][1]);
            }
        }
        __syncthreads();
    }

    float* cs = (float*)smem;   // [128][132]
    const float inv64 = 1.0f / 64.0f;
#pragma unroll
    for (int mt = 0; mt < 4; mt++) {
#pragma unroll
        for (int nt = 0; nt < 4; nt++) {
            const int r = wm * 64 + mt * 16 + qrow;
            const int c = wn * 32 + nt * 8 + (lane & 3) * 2;
            cs[r * 132 + c]           = alpha * (acc[mt][nt][0] + axx[mt][nt][0] * inv64);
            cs[r * 132 + c + 1]       = alpha * (acc[mt][nt][1] + axx[mt][nt][1] * inv64);
            cs[(r + 8) * 132 + c]     = alpha * (acc[mt][nt][2] + axx[mt][nt][2] * inv64);
            cs[(r + 8) * 132 + c + 1] = alpha * (acc[mt][nt][3] + axx[mt][nt][3] * inv64);
        }
    }
    __syncthreads();
    {
        const int row = tid >> 1;
        const int hf  = tid & 1;
        const float4* srow = (const float4*)(cs + row * 132 + hf * 64);
        const long cbase = zb * strCb + zh * strCh + (m0 + row) * (long)ldc + n0 + hf * 64;
        if (EMIT == 0) {
            float4* crow = (float4*)(Cf + cbase);
#pragma unroll
            for (int i = 0; i < 16; i++) crow[i] = srow[i];
        } else {
            __half2* hrow = (__half2*)(Chi + cbase);
            __half2* lrow = (EMIT == 1) ? (__half2*)(Clo + cbase) : nullptr;
#pragma unroll
            for (int i = 0; i < 16; i++) {
                float4 v = srow[i];
                __half hx = __float2half_rn(v.x), hy = __float2half_rn(v.y);
                __half hz = __float2half_rn(v.z), hw = __float2half_rn(v.w);
                hrow[2 * i]     = __halves2half2(hx, hy);
                hrow[2 * i + 1] = __halves2half2(hz, hw);
                if (EMIT == 1) {
                    __half lx = __float2half_rn((v.x - __half2float(hx)) * 64.f);
                    __half ly = __float2half_rn((v.y - __half2float(hy)) * 64.f);
                    __half lz = __float2half_rn((v.z - __half2float(hz)) * 64.f);
                    __half lw = __float2half_rn((v.w - __half2float(hw)) * 64.f);
                    lrow[2 * i]     = __halves2half2(lx, ly);
                    lrow[2 * i + 1] = __halves2half2(lz, lw);
                }
            }
        }
    }
}

// =================== WIDE 1-prod HMMA GEMM (128x256 tile): C = A * B^T =====
// Pure fp16 product (Ahi*Bhi). 8 warps as 2M x 4N, warp tile 64x64.
// Per k-step: 32 LDS / 32 MMA per warp -> balanced (vs 24/16 in narrow tile).
// EMIT: 0 = fp32; 1 = fp16 hi+lo; 2 = fp16 hi only.
#define STGW (PLANE_B + PLANE_BW)    // 30720 per stage

template<int EMIT>
__global__ __launch_bounds__(256, 1) void hgemm_w(
    const __half* __restrict__ Ahi, const __half* __restrict__ Bhi,
    float* __restrict__ Cf, __half* __restrict__ Chi, __half* __restrict__ Clo,
    int lda, int ldb, int ldc, int Kd)
{
    extern __shared__ char smem[];
    const uint32_t smb = smem_u32(smem);
    const int tid  = threadIdx.x;
    const int wid  = tid >> 5;
    const int lane = tid & 31;
    const int wm   = wid & 1;        // 2 warps along M (64 each)
    const int wn   = wid >> 1;       // 4 warps along N (64 each)
    const int qrow = lane >> 2;
    const int qk   = (lane & 3) * 2;

    const long m0 = (long)blockIdx.y * 128;
    const long n0 = (long)blockIdx.x * 256;

    const __half* gA = Ahi + m0 * lda;
    const __half* gB = Bhi + n0 * ldb;

    const int r0 = tid >> 2, s0 = tid & 3;

    float acc[4][8][4];
#pragma unroll
    for (int i = 0; i < 4; i++)
#pragma unroll
        for (int j = 0; j < 8; j++)
#pragma unroll
            for (int r = 0; r < 4; r++) acc[i][j][r] = 0.f;

    const int NC = Kd / 32;

    // prologue: A 128 rows (2/thread), B 256 rows (4/thread)
    cp16(smb + r0 * (SKW * 2) + s0 * 16, gA + (long)r0 * lda + s0 * 8);
    cp16(smb + (r0 + 64) * (SKW * 2) + s0 * 16, gA + (long)(r0 + 64) * lda + s0 * 8);
#pragma unroll
    for (int q = 0; q < 4; q++)
        cp16(smb + PLANE_B + (r0 + q * 64) * (SKW * 2) + s0 * 16,
             gB + (long)(r0 + q * 64) * ldb + s0 * 8);
    cp_commit();

    for (int ch = 0; ch < NC; ch++) {
        const int st = ch & 1;
        if (ch + 1 < NC) {
            const int k0 = (ch + 1) * 32;
            const uint32_t sb = smb + (st ^ 1) * STGW;
            cp16(sb + r0 * (SKW * 2) + s0 * 16, gA + (long)r0 * lda + k0 + s0 * 8);
            cp16(sb + (r0 + 64) * (SKW * 2) + s0 * 16, gA + (long)(r0 + 64) * lda + k0 + s0 * 8);
#pragma unroll
            for (int q = 0; q < 4; q++)
                cp16(sb + PLANE_B + (r0 + q * 64) * (SKW * 2) + s0 * 16,
                     gB + (long)(r0 + q * 64) * ldb + k0 + s0 * 8);
            cp_commit();
            cp_wait<1>();
        } else {
            cp_wait<0>();
        }
        __syncthreads();

        const uint32_t* pA = (const uint32_t*)(smem + st * STGW);
        const uint32_t* pB = (const uint32_t*)(smem + st * STGW + PLANE_B);

#pragma unroll
        for (int ks = 0; ks < 2; ks++) {
            const int kb = ks * 16;
            uint32_t af[4][4], bf[8][2];
#pragma unroll
            for (int mt = 0; mt < 4; mt++) {
                const int mr = wm * 64 + mt * 16 + qrow;
                af[mt][0] = pA[(mr * SKW + kb + qk) >> 1];
                af[mt][1] = pA[((mr + 8) * SKW + kb + qk) >> 1];
                af[mt][2] = pA[(mr * SKW + kb + qk + 8) >> 1];
                af[mt][3] = pA[((mr + 8) * SKW + kb + qk + 8) >> 1];
            }
#pragma unroll
            for (int nt = 0; nt < 8; nt++) {
                const int nr = wn * 64 + nt * 8 + qrow;
                bf[nt][0] = pB[(nr * SKW + kb + qk) >> 1];
                bf[nt][1] = pB[(nr * SKW + kb + qk + 8) >> 1];
            }
#pragma unroll
            for (int mt = 0; mt < 4; mt++)
#pragma unroll
                for (int nt = 0; nt < 8; nt++)
                    mma16816(acc[mt][nt], af[mt], bf[nt][0], bf[nt][1]);
        }
        __syncthreads();
    }

    // ---- epilogue: stage fp32 in smem [128][260], emit per EMIT ----
    float* cs = (float*)smem;
#pragma unroll
    for (int mt = 0; mt < 4; mt++) {
#pragma unroll
        for (int nt = 0; nt < 8; nt++) {
            const int r = wm * 64 + mt * 16 + qrow;
            const int c = wn * 64 + nt * 8 + (lane & 3) * 2;
            cs[r * 260 + c]           = acc[mt][nt][0];
            cs[r * 260 + c + 1]       = acc[mt][nt][1];
            cs[(r + 8) * 260 + c]     = acc[mt][nt][2];
            cs[(r + 8) * 260 + c + 1] = acc[mt][nt][3];
        }
    }
    __syncthreads();
    {
        const int row = tid >> 1;
        const int hf  = tid & 1;
        const float4* srow = (const float4*)(cs + row * 260 + hf * 128);
        const long cbase = (m0 + row) * (long)ldc + n0 + hf * 128;
        if (EMIT == 0) {
            float4* crow = (float4*)(Cf + cbase);
#pragma unroll
            for (int i = 0; i < 32; i++) crow[i] = srow[i];
        } else {
            __half2* hrow = (__half2*)(Chi + cbase);
            __half2* lrow = (EMIT == 1) ? (__half2*)(Clo + cbase) : nullptr;
#pragma unroll
            for (int i = 0; i < 32; i++) {
                float4 v = srow[i];
                __half hx = __float2half_rn(v.x), hy = __float2half_rn(v.y);
                __half hz = __float2half_rn(v.z), hw = __float2half_rn(v.w);
                hrow[2 * i]     = __halves2half2(hx, hy);
                hrow[2 * i + 1] = __halves2half2(hz, hw);
                if (EMIT == 1) {
                    __half lx = __float2half_rn((v.x - __half2float(hx)) * 64.f);
                    __half ly = __float2half_rn((v.y - __half2float(hy)) * 64.f);
                    __half lz = __float2half_rn((v.z - __half2float(hz)) * 64.f);
                    __half lw = __float2half_rn((v.w - __half2float(hw)) * 64.f);
                    lrow[2 * i]     = __halves2half2(lx, ly);
                    lrow[2 * i + 1] = __halves2half2(lz, lw);
                }
            }
        }
    }
}

// ---------------- score-net stage 2 ----------------
__global__ void score_stage2(const float* __restrict__ hidden,
                             const float* __restrict__ sb1,
                             const float* __restrict__ sw2,
                             const float* __restrict__ sb2,
                             float* __restrict__ out, int nrows)
{
    int warp = (blockIdx.x * blockDim.x + threadIdx.x) >> 5;
    int lane = threadIdx.x & 31;
    if (warp >= nrows) return;
    const float4 hv = ((const float4*)(hidden + (long)warp * 128))[lane];
    const float4 b1 = ((const float4*)sb1)[lane];
    const float4 w2 = ((const float4*)sw2)[lane];
    float s = fmaxf(hv.x + b1.x, 0.f) * w2.x
            + fmaxf(hv.y + b1.y, 0.f) * w2.y
            + fmaxf(hv.z + b1.z, 0.f) * w2.z
            + fmaxf(hv.w + b1.w, 0.f) * w2.w;
#pragma unroll
    for (int o = 16; o > 0; o >>= 1) s += __shfl_xor_sync(0xFFFFFFFFu, s, o);
    if (lane == 0) out[warp] = s + sb2[0];
}

// ---------------- sparsek projection + exact top-128 ----------------
__device__ __forceinline__ unsigned enc_desc(float v) {
    unsigned b = __float_as_uint(v);
    unsigned o = (b & 0x80000000u) ? ~b : (b | 0x80000000u);
    return ~o;
}
__device__ __forceinline__ float dec_desc(unsigned d) {
    unsigned o = ~d;
    unsigned b = (o & 0x80000000u) ? (o ^ 0x80000000u) : ~o;
    return __uint_as_float(b);
}

__global__ __launch_bounds__(1024) void sparsek_topk(const float* __restrict__ scores,
                                                     int* __restrict__ out_idx)
{
    __shared__ unsigned long long key[SS];
    __shared__ unsigned char flag[SS];
    __shared__ float fred[32];
    __shared__ int   ired[32];
    __shared__ int   rho_s, npos_s;
    __shared__ float tau_s;
    int bh  = blockIdx.x;
    int tid = threadIdx.x;
    int lane = tid & 31, warp = tid >> 5;
    const float* s = scores + (long)bh * SS;

    for (int i = tid; i < SS; i += 1024)
        key[i] = ((unsigned long long)enc_desc(s[i]) << 32) | (unsigned)i;
    __syncthreads();

    for (int k = 2; k <= SS; k <<= 1) {
        for (int j = k >> 1; j > 0; j >>= 1) {
            for (int i = tid; i < SS; i += 1024) {
                int ixj = i ^ j;
                if (ixj > i) {
                    bool up = ((i & k) == 0);
                    unsigned long long a = key[i], b = key[ixj];
                    if ((a > b) == up) { key[i] = b; key[ixj] = a; }
                }
            }
            __syncthreads();
        }
    }

    float v[4], pc[4];
#pragma unroll
    for (int j = 0; j < 4; j++) v[j] = dec_desc((unsigned)(key[tid * 4 + j] >> 32));
    pc[0] = v[0]; pc[1] = pc[0] + v[1]; pc[2] = pc[1] + v[2]; pc[3] = pc[2] + v[3];
    float tot = pc[3];
#pragma unroll
    for (int o = 1; o < 32; o <<= 1) {
        float n = __shfl_up_sync(0xFFFFFFFFu, tot, o);
        if (lane >= o) tot += n;
    }
    if (lane == 31) fred[warp] = tot;
    __syncthreads();
    if (warp == 0) {
        float w = fred[lane];
#pragma unroll
        for (int o = 1; o < 32; o <<= 1) {
            float n = __shfl_up_sync(0xFFFFFFFFu, w, o);
            if (lane >= o) w += n;
        }
        fred[lane] = w;
    }
    __syncthreads();
    const float base = (warp ? fred[warp - 1] : 0.f) + (tot - pc[3]);

    int cnt = 0;
#pragma unroll
    for (int j = 0; j < 4; j++) {
        float csj = base + pc[j];
        float thr = (csj - (float)KSEL) / (float)(tid * 4 + j + 1);
        if (v[j] > thr) cnt++;
    }
#pragma unroll
    for (int o = 16; o > 0; o >>= 1) cnt += __shfl_xor_sync(0xFFFFFFFFu, cnt, o);
    if (lane == 0) ired[warp] = cnt;
    __syncthreads();
    if (tid == 0) {
        int r = 0;
#pragma unroll
        for (int i = 0; i < 32; i++) r += ired[i];
        rho_s = (r < 1) ? 1 : r;
    }
    __syncthreads();
    const int rho = rho_s;
    {
        int rr = rho - 1;
        if ((rr >> 2) == tid)
            tau_s = (base + pc[rr & 3] - (float)KSEL) / (float)rho;
    }
    __syncthreads();
    const float tau = tau_s;
    int cnp = 0;
#pragma unroll
    for (int j = 0; j < 4; j++) if (v[j] > tau) cnp++;
#pragma unroll
    for (int o = 16; o > 0; o >>= 1) cnp += __shfl_xor_sync(0xFFFFFFFFu, cnp, o);
    if (lane == 0) ired[warp] = cnp;
    __syncthreads();
    if (tid == 0) {
        int r = 0;
#pragma unroll
        for (int i = 0; i < 32; i++) r += ired[i];
        npos_s = r;
    }
    __syncthreads();

    const int npos = npos_s;
    if (npos >= KSEL) {
        if (tid < KSEL)
            out_idx[bh * KSEL + tid] = (int)(key[tid] & 0xFFFFFFFFu);
    } else {
        if (tid < npos)
            out_idx[bh * KSEL + tid] = (int)(key[tid] & 0xFFFFFFFFu);
        for (int i = tid; i < SS; i += 1024) flag[i] = 0;
        __syncthreads();
        for (int i = tid; i < npos; i += 1024)
            flag[key[i] & 0xFFFFFFFFu] = 1;
        __syncthreads();
        if (tid == 0) {
            int c2 = npos;
            for (int i = 0; i < SS && c2 < KSEL; i++)
                if (!flag[i]) out_idx[bh * KSEL + c2++] = i;
        }
    }
}

// ---------------- gather selected K / V^T from split planes ----------------
__global__ void gather_kv_h(const __half* __restrict__ Khi, const __half* __restrict__ Klo,
                            const __half* __restrict__ Vhi, const __half* __restrict__ Vlo,
                            const int* __restrict__ idx,
                            __half* __restrict__ kh, __half* __restrict__ kl,
                            __half* __restrict__ vth, __half* __restrict__ vtl)
{
    int bh = blockIdx.x >> 7;
    int j  = blockIdx.x & 127;
    int d  = threadIdx.x;
    int b  = bh >> 4, h = bh & 15;
    int row = idx[bh * KSEL + j];
    long src = ((long)(b * SS + row)) * HH + (long)h * HDIM + d;
    long kd = (long)bh * (KSEL * HDIM) + (long)j * HDIM + d;
    long vd = (long)bh * (KSEL * HDIM) + (long)d * KSEL + j;
    kh[kd]  = Khi[src];
    kl[kd]  = Klo[src];
    vth[vd] = Vhi[src];
    vtl[vd] = Vlo[src];
}

// ---------------- softmax over rows of 128, fp16 hi output ----------------
__global__ void softmax_h(const float* __restrict__ p,
                          __half* __restrict__ phi, int nrows)
{
    int warp = (blockIdx.x * blockDim.x + threadIdx.x) >> 5;
    int lane = threadIdx.x & 31;
    if (warp >= nrows) return;
    float4 v = ((const float4*)(p + (long)warp * 128))[lane];
    float m = fmaxf(fmaxf(v.x, v.y), fmaxf(v.z, v.w));
#pragma unroll
    for (int o = 16; o > 0; o >>= 1) m = fmaxf(m, __shfl_xor_sync(0xFFFFFFFFu, m, o));
    v.x = expf(v.x - m); v.y = expf(v.y - m);
    v.z = expf(v.z - m); v.w = expf(v.w - m);
    float sum = v.x + v.y + v.z + v.w;
#pragma unroll
    for (int o = 16; o > 0; o >>= 1) sum += __shfl_xor_sync(0xFFFFFFFFu, sum, o);
    float inv = 1.0f / sum;
    __half2* ph = (__half2*)(phi + (long)warp * 128 + lane * 4);
    ph[0] = __halves2half2(__float2half_rn(v.x * inv), __float2half_rn(v.y * inv));
    ph[1] = __halves2half2(__float2half_rn(v.z * inv), __float2half_rn(v.w * inv));
}

// ---------------- launch ----------------
extern "C" void kernel_launch(void* const* d_in, const int* in_sizes, int n_in,
                              void* d_out, int out_size)
{
    const float* x   = (const float*)d_in[0];
    const float* wq  = (const float*)d_in[1];
    const float* wk  = (const float*)d_in[2];
    const float* wv  = (const float*)d_in[3];
    const float* wo  = (const float*)d_in[4];
    const float* sw1 = (const float*)d_in[5];
    const float* sb1 = (const float*)d_in[6];
    const float* sw2 = (const float*)d_in[7];
    const float* sb2 = (const float*)d_in[8];
    float* out = (float*)d_out;

    float *pTmp, *pScores;
    int* pIdx;
    __half *pXhi, *pXlo, *pQhi, *pKhi, *pKlo, *pVhi, *pVlo, *pPhi, *pOhi, *pWhi, *pWlo;
    __half *pKselh, *pKsell, *pVselTh, *pVselTl;
    cudaGetSymbolAddress((void**)&pTmp,    gTmp);
    cudaGetSymbolAddress((void**)&pScores, gScores);
    cudaGetSymbolAddress((void**)&pIdx,    gIdx);
    cudaGetSymbolAddress((void**)&pXhi,    gXhi);
    cudaGetSymbolAddress((void**)&pXlo,    gXlo);
    cudaGetSymbolAddress((void**)&pQhi,    gQhi);
    cudaGetSymbolAddress((void**)&pKhi,    gKhi);
    cudaGetSymbolAddress((void**)&pKlo,    gKlo);
    cudaGetSymbolAddress((void**)&pVhi,    gVhi);
    cudaGetSymbolAddress((void**)&pVlo,    gVlo);
    cudaGetSymbolAddress((void**)&pPhi,    gPhi);
    cudaGetSymbolAddress((void**)&pOhi,    gOhi);
    cudaGetSymbolAddress((void**)&pWhi,    gWhi);
    cudaGetSymbolAddress((void**)&pWlo,    gWlo);
    cudaGetSymbolAddress((void**)&pKselh,  gKselh);
    cudaGetSymbolAddress((void**)&pKsell,  gKsell);
    cudaGetSymbolAddress((void**)&pVselTh, gVselTh);
    cudaGetSymbolAddress((void**)&pVselTl, gVselTl);

    const int SM2 = 67584;    // max(2*3*10240, 128*132*4)
    const int SM3 = 81920;    // 2*4*10240
    const int SMW = 133120;   // max(2*30720, 128*260*4)
    cudaFuncSetAttribute(hgemm_w<0>, cudaFuncAttributeMaxDynamicSharedMemorySize, SMW);
    cudaFuncSetAttribute(hgemm_w<1>, cudaFuncAttributeMaxDynamicSharedMemorySize, SMW);
    cudaFuncSetAttribute(hgemm_w<2>, cudaFuncAttributeMaxDynamicSharedMemorySize, SMW);
    cudaFuncSetAttribute(hgemm<2,0>, cudaFuncAttributeMaxDynamicSharedMemorySize, SM2);
    cudaFuncSetAttribute(hgemm<2,2>, cudaFuncAttributeMaxDynamicSharedMemorySize, SM2);
    cudaFuncSetAttribute(hgemm<3,0>, cudaFuncAttributeMaxDynamicSharedMemorySize, SM3);
    cudaFuncSetAttribute(hgemm<3,1>, cudaFuncAttributeMaxDynamicSharedMemorySize, SM3);

    const long sBH  = (long)SS * HH;
    const long sHd  = HDIM;
    const long sTb  = (long)NHEADS * SS * HDIM;
    const long sTh  = (long)SS * HDIM;
    const long sSelb = (long)KSEL * HDIM * NHEADS;
    const long sSelh = (long)KSEL * HDIM;

    dim3 gProj(HH / 128, NROWS / 128, 1);   // (16, 64, 1) narrow
    dim3 gProjW(HH / 256, NROWS / 128, 1);  // (8, 64, 1) wide
    dim3 gAtt(1, SS / 128, NBH);            // (1, 32, 32)

    // ---- split X (lo needed only for K projection) ----
    split2h<<<(int)((ROWHID + 255) / 256), 256>>>(x, pXhi, pXlo, ROWHID);

    // ---- Q = X @ wq^T (1-prod wide, emit hi only) ----
    split1h<<<(int)((WN + 255) / 256), 256>>>(wq, pWhi, WN);
    hgemm_w<2><<<gProjW, 256, SMW>>>(pXhi, pWhi, nullptr, pQhi, nullptr, HH, HH, HH, HH);
    // ---- K = X @ wk^T (3-prod, protects selection; emit hi+lo) ----
    split2h<<<(int)((WN + 255) / 256), 256>>>(wk, pWhi, pWlo, WN);
    hgemm<3,1><<<gProj, 256, SM3>>>(pXhi, pXlo, pWhi, pWlo, nullptr, pKhi, pKlo,
                                    HH, HH, HH, 0, 0, 0, 0, 0, 0, HH, 1.0f);
    // ---- V = X @ wv^T (1-prod wide, emit hi+lo splits of result) ----
    split1h<<<(int)((WN + 255) / 256), 256>>>(wv, pWhi, WN);
    hgemm_w<1><<<gProjW, 256, SMW>>>(pXhi, pWhi, nullptr, pVhi, pVlo, HH, HH, HH, HH);

    // ---- score-net hidden = K_head @ sw1^T (3-prod batched, fp32 out) ----
    split2h<<<(int)(((long)HDIM * HDIM + 255) / 256), 256>>>(sw1, pWhi, pWlo, (long)HDIM * HDIM);
    hgemm<3,0><<<gAtt, 256, SM3>>>(pKhi, pKlo, pWhi, pWlo, pTmp, nullptr, nullptr,
                                   HH, HDIM, HDIM,
                                   sBH, sHd, 0, 0, sTb, sTh, HDIM, 1.0f);
    score_stage2<<<(NBH * SS) / 8, 256>>>(pTmp, sb1, sw2, sb2, pScores, NBH * SS);
    sparsek_topk<<<NBH, 1024>>>(pScores, pIdx);
    gather_kv_h<<<NBH * KSEL, HDIM>>>(pKhi, pKlo, pVhi, pVlo, pIdx,
                                      pKselh, pKsell, pVselTh, pVselTl);

    // ---- attn scores = Q_head @ Ksel^T * scale (2-prod batched, fp32 out) ----
    const float scale = 0.08838834764831845f;
    hgemm<2,0><<<gAtt, 256, SM2>>>(pQhi, nullptr, pKselh, pKsell, pTmp, nullptr, nullptr,
                                   HH, HDIM, HDIM,
                                   sBH, sHd, sSelb, sSelh, sTb, sTh, HDIM, scale);
    softmax_h<<<(NBH * SS) / 8, 256>>>(pTmp, pPhi, NBH * SS);

    // ---- out_head = P @ Vsel (2-prod batched, emit hi), [B,S,H] layout ----
    hgemm<2,2><<<gAtt, 256, SM2>>>(pPhi, nullptr, pVselTh, pVselTl, nullptr, pOhi, nullptr,
                                   HDIM, KSEL, HH,
                                   sTb, sTh, sSelb, sSelh, sBH, sHd, KSEL, 1.0f);

    // ---- out = O @ wo^T (1-prod wide, fp32 out) ----
    split1h<<<(int)((WN + 255) / 256), 256>>>(wo, pWhi, WN);
    hgemm_w<0><<<gProjW, 256, SMW>>>(pOhi, pWhi, out, nullptr, nullptr, HH, HH, HH, HH);
}

// round 9
// speedup vs baseline: 1.1778x; 1.1778x over previous
#include <cuda_runtime.h>
#include <cuda_fp16.h>
#include <math.h>
#include <stdint.h>

// ---------------- problem constants ----------------
#define BB        2
#define SS        4096
#define HH        2048
#define NHEADS    16
#define HDIM      128
#define KSEL      128
#define NROWS     (BB*SS)            // 8192
#define NBH       (BB*NHEADS)        // 32
#define ROWHID    ((long)NROWS*HH)   // 16777216
#define WN        ((long)HH*HH)      // 4194304
#define SELN      (NBH*KSEL*HDIM)    // 524288
#define XSELN     ((long)NBH*KSEL*HH) // 8388608

// ---------------- scratch (device globals; no allocs allowed) ----------------
__device__ float  gTmp[ROWHID];          // hidden, then attn scores (fp32)
__device__ float  gScores[NBH*SS];
__device__ int    gIdx[NBH*KSEL];
__device__ __half gXhi[ROWHID];
__device__ __half gXlo[ROWHID];
__device__ __half gQhi[ROWHID];
__device__ __half gKhi[ROWHID];
__device__ __half gKlo[ROWHID];
__device__ __half gPhi[ROWHID];
__device__ __half gOhi[ROWHID];
__device__ __half gWhi[WN];
__device__ __half gWlo[WN];
__device__ __half gXsel[XSELN];
__device__ __half gKselh[SELN];
__device__ __half gKsell[SELN];
__device__ __half gVselTh[SELN];
__device__ __half gVselTl[SELN];

// =================== helpers ===================
__device__ __forceinline__ uint32_t smem_u32(const void* p) {
    uint32_t a;
    asm("{ .reg .u64 t; cvta.to.shared.u64 t, %1; cvt.u32.u64 %0, t; }" : "=r"(a) : "l"(p));
    return a;
}
__device__ __forceinline__ void cp16(uint32_t dst, const void* src) {
    asm volatile("cp.async.cg.shared.global [%0], [%1], 16;" :: "r"(dst), "l"(src));
}
__device__ __forceinline__ void cp_commit() {
    asm volatile("cp.async.commit_group;" ::: "memory");
}
template<int N>
__device__ __forceinline__ void cp_wait() {
    asm volatile("cp.async.wait_group %0;" :: "n"(N) : "memory");
}
__device__ __forceinline__ void mma16816(float* c, const uint32_t* a, uint32_t b0, uint32_t b1) {
    asm volatile(
        "mma.sync.aligned.m16n8k16.row.col.f32.f16.f16.f32 "
        "{%0,%1,%2,%3}, {%4,%5,%6,%7}, {%8,%9}, {%0,%1,%2,%3};"
        : "+f"(c[0]), "+f"(c[1]), "+f"(c[2]), "+f"(c[3])
        : "r"(a[0]), "r"(a[1]), "r"(a[2]), "r"(a[3]), "r"(b0), "r"(b1));
}

// =================== splits ===================
__global__ void split2h(const float* __restrict__ s, __half* __restrict__ hi,
                        __half* __restrict__ lo, long n)
{
    long i = (long)blockIdx.x * blockDim.x + threadIdx.x;
    if (i >= n) return;
    float x = s[i];
    __half h = __float2half_rn(x);
    hi[i] = h;
    lo[i] = __float2half_rn((x - __half2float(h)) * 64.0f);
}
__global__ void split1h(const float* __restrict__ s, __half* __restrict__ hi, long n)
{
    long i = (long)blockIdx.x * blockDim.x + threadIdx.x;
    if (i >= n) return;
    hi[i] = __float2half_rn(s[i]);
}

#define SKW 40
#define PLANE_B (128 * SKW * 2)      // 10240 bytes
#define PLANE_BW (256 * SKW * 2)     // 20480 bytes (wide B tile)

// =================== HMMA split GEMM (128x128 tile): C = alpha * A * B^T ====
// NPROD==3: C ~= Ahi*Bhi + (Ahi*Blo + Alo*Bhi)/64
// NPROD==2: C ~= Ahi*Bhi + (Ahi*Blo)/64
// NPROD==1: C ~= Ahi*Bhi
// EMIT: 0 = fp32 to Cf; 1 = fp16 hi+lo planes (Chi,Clo); 2 = fp16 hi only.
// Batched via blockIdx.z (zb=z>>4, zh=z&15).
template<int NPROD, int EMIT>
__global__ __launch_bounds__(256, 1) void hgemm(
    const __half* __restrict__ Ahi, const __half* __restrict__ Alo,
    const __half* __restrict__ Bhi, const __half* __restrict__ Blo,
    float* __restrict__ Cf, __half* __restrict__ Chi, __half* __restrict__ Clo,
    int lda, int ldb, int ldc,
    long strAb, long strAh, long strBb, long strBh, long strCb, long strCh,
    int Kd, float alpha)
{
    constexpr int NPL = (NPROD == 3) ? 4 : (NPROD == 2 ? 3 : 2);
    constexpr int STG = NPL * PLANE_B;
    extern __shared__ char smem[];
    const uint32_t smb = smem_u32(smem);
    const int tid  = threadIdx.x;
    const int wid  = tid >> 5;
    const int lane = tid & 31;
    const int wm   = wid & 1;
    const int wn   = wid >> 1;
    const int qrow = lane >> 2;
    const int qk   = (lane & 3) * 2;

    const int z = blockIdx.z, zb = z >> 4, zh = z & 15;
    const long m0 = (long)blockIdx.y * 128;
    const long n0 = (long)blockIdx.x * 128;

    const __half* pg[4];
    int pld[4];
    pg[0] = Ahi + zb * strAb + zh * strAh + m0 * lda;  pld[0] = lda;
    pg[1] = Bhi + zb * strBb + zh * strBh + n0 * ldb;  pld[1] = ldb;
    pg[2] = (NPROD >= 2) ? (Blo + zb * strBb + zh * strBh + n0 * ldb) : pg[1];
    pld[2] = ldb;
    pg[3] = (NPROD == 3) ? (Alo + zb * strAb + zh * strAh + m0 * lda) : pg[0];
    pld[3] = lda;

    const int r0 = tid >> 2, s0 = tid & 3;
    const int r1 = r0 + 64;

    float acc[4][4][4], axx[4][4][4];
#pragma unroll
    for (int i = 0; i < 4; i++)
#pragma unroll
        for (int j = 0; j < 4; j++)
#pragma unroll
            for (int r = 0; r < 4; r++) { acc[i][j][r] = 0.f; axx[i][j][r] = 0.f; }

    const int NC = Kd / 32;

#pragma unroll
    for (int p = 0; p < NPL; p++) {
        cp16(smb + p * PLANE_B + r0 * (SKW * 2) + s0 * 16, pg[p] + (long)r0 * pld[p] + s0 * 8);
        cp16(smb + p * PLANE_B + r1 * (SKW * 2) + s0 * 16, pg[p] + (long)r1 * pld[p] + s0 * 8);
    }
    cp_commit();

    for (int ch = 0; ch < NC; ch++) {
        const int st = ch & 1;
        if (ch + 1 < NC) {
            const int k0 = (ch + 1) * 32;
            const uint32_t sb = smb + (st ^ 1) * STG;
#pragma unroll
            for (int p = 0; p < NPL; p++) {
                cp16(sb + p * PLANE_B + r0 * (SKW * 2) + s0 * 16, pg[p] + (long)r0 * pld[p] + k0 + s0 * 8);
                cp16(sb + p * PLANE_B + r1 * (SKW * 2) + s0 * 16, pg[p] + (long)r1 * pld[p] + k0 + s0 * 8);
            }
            cp_commit();
            cp_wait<1>();
        } else {
            cp_wait<0>();
        }
        __syncthreads();

        const uint32_t* pAh = (const uint32_t*)(smem + st * STG + 0 * PLANE_B);
        const uint32_t* pBh = (const uint32_t*)(smem + st * STG + 1 * PLANE_B);
        const uint32_t* pBl = (const uint32_t*)(smem + st * STG + 2 * PLANE_B);
        const uint32_t* pAl = (const uint32_t*)(smem + st * STG + 3 * PLANE_B);

#pragma unroll
        for (int ks = 0; ks < 2; ks++) {
            const int kb = ks * 16;
            uint32_t af[4][4], bf[4][2];
#pragma unroll
            for (int mt = 0; mt < 4; mt++) {
                const int mr = wm * 64 + mt * 16 + qrow;
                af[mt][0] = pAh[(mr * SKW + kb + qk) >> 1];
                af[mt][1] = pAh[((mr + 8) * SKW + kb + qk) >> 1];
                af[mt][2] = pAh[(mr * SKW + kb + qk + 8) >> 1];
                af[mt][3] = pAh[((mr + 8) * SKW + kb + qk + 8) >> 1];
            }
#pragma unroll
            for (int nt = 0; nt < 4; nt++) {
                const int nr = wn * 32 + nt * 8 + qrow;
                bf[nt][0] = pBh[(nr * SKW + kb + qk) >> 1];
                bf[nt][1] = pBh[(nr * SKW + kb + qk + 8) >> 1];
            }
#pragma unroll
            for (int mt = 0; mt < 4; mt++)
#pragma unroll
                for (int nt = 0; nt < 4; nt++)
                    mma16816(acc[mt][nt], af[mt], bf[nt][0], bf[nt][1]);
            if (NPROD >= 2) {
                uint32_t bl[4][2];
#pragma unroll
                for (int nt = 0; nt < 4; nt++) {
                    const int nr = wn * 32 + nt * 8 + qrow;
                    bl[nt][0] = pBl[(nr * SKW + kb + qk) >> 1];
                    bl[nt][1] = pBl[(nr * SKW + kb + qk + 8) >> 1];
                }
#pragma unroll
                for (int mt = 0; mt < 4; mt++)
#pragma unroll
                    for (int nt = 0; nt < 4; nt++)
                        mma16816(axx[mt][nt], af[mt], bl[nt][0], bl[nt][1]);
            }
            if (NPROD == 3) {
#pragma unroll
                for (int mt = 0; mt < 4; mt++) {
                    const int mr = wm * 64 + mt * 16 + qrow;
                    af[mt][0] = pAl[(mr * SKW + kb + qk) >> 1];
                    af[mt][1] = pAl[((mr + 8) * SKW + kb + qk) >> 1];
                    af[mt][2] = pAl[(mr * SKW + kb + qk + 8) >> 1];
                    af[mt][3] = pAl[((mr + 8) * SKW + kb + qk + 8) >> 1];
                }
#pragma unroll
                for (int mt = 0; mt < 4; mt++)
#pragma unroll
                    for (int nt = 0; nt < 4; nt++)
                        mma16816(axx[mt][nt], af[mt], bf[nt][0], bf[nt][1]);
            }
        }
        __syncthreads();
    }

    float* cs = (float*)smem;   // [128][132]
    const float inv64 = 1.0f / 64.0f;
#pragma unroll
    for (int mt = 0; mt < 4; mt++) {
#pragma unroll
        for (int nt = 0; nt < 4; nt++) {
            const int r = wm * 64 + mt * 16 + qrow;
            const int c = wn * 32 + nt * 8 + (lane & 3) * 2;
            if (NPROD >= 2) {
                cs[r * 132 + c]           = alpha * (acc[mt][nt][0] + axx[mt][nt][0] * inv64);
                cs[r * 132 + c + 1]       = alpha * (acc[mt][nt][1] + axx[mt][nt][1] * inv64);
                cs[(r + 8) * 132 + c]     = alpha * (acc[mt][nt][2] + axx[mt][nt][2] * inv64);
                cs[(r + 8) * 132 + c + 1] = alpha * (acc[mt][nt][3] + axx[mt][nt][3] * inv64);
            } else {
                cs[r * 132 + c]           = alpha * acc[mt][nt][0];
                cs[r * 132 + c + 1]       = alpha * acc[mt][nt][1];
                cs[(r + 8) * 132 + c]     = alpha * acc[mt][nt][2];
                cs[(r + 8) * 132 + c + 1] = alpha * acc[mt][nt][3];
            }
        }
    }
    __syncthreads();
    {
        const int row = tid >> 1;
        const int hf  = tid & 1;
        const float4* srow = (const float4*)(cs + row * 132 + hf * 64);
        const long cbase = zb * strCb + zh * strCh + (m0 + row) * (long)ldc + n0 + hf * 64;
        if (EMIT == 0) {
            float4* crow = (float4*)(Cf + cbase);
#pragma unroll
            for (int i = 0; i < 16; i++) crow[i] = srow[i];
        } else {
            __half2* hrow = (__half2*)(Chi + cbase);
            __half2* lrow = (EMIT == 1) ? (__half2*)(Clo + cbase) : nullptr;
#pragma unroll
            for (int i = 0; i < 16; i++) {
                float4 v = srow[i];
                __half hx = __float2half_rn(v.x), hy = __float2half_rn(v.y);
                __half hz = __float2half_rn(v.z), hw = __float2half_rn(v.w);
                hrow[2 * i]     = __halves2half2(hx, hy);
                hrow[2 * i + 1] = __halves2half2(hz, hw);
                if (EMIT == 1) {
                    __half lx = __float2half_rn((v.x - __half2float(hx)) * 64.f);
                    __half ly = __float2half_rn((v.y - __half2float(hy)) * 64.f);
                    __half lz = __float2half_rn((v.z - __half2float(hz)) * 64.f);
                    __half lw = __float2half_rn((v.w - __half2float(hw)) * 64.f);
                    lrow[2 * i]     = __halves2half2(lx, ly);
                    lrow[2 * i + 1] = __halves2half2(lz, lw);
                }
            }
        }
    }
}

// =================== WIDE 1-prod HMMA GEMM (128x256 tile): C = A * B^T =====
#define STGW (PLANE_B + PLANE_BW)    // 30720 per stage

template<int EMIT>
__global__ __launch_bounds__(256, 1) void hgemm_w(
    const __half* __restrict__ Ahi, const __half* __restrict__ Bhi,
    float* __restrict__ Cf, __half* __restrict__ Chi, __half* __restrict__ Clo,
    int lda, int ldb, int ldc, int Kd)
{
    extern __shared__ char smem[];
    const uint32_t smb = smem_u32(smem);
    const int tid  = threadIdx.x;
    const int wid  = tid >> 5;
    const int lane = tid & 31;
    const int wm   = wid & 1;
    const int wn   = wid >> 1;
    const int qrow = lane >> 2;
    const int qk   = (lane & 3) * 2;

    const long m0 = (long)blockIdx.y * 128;
    const long n0 = (long)blockIdx.x * 256;

    const __half* gA = Ahi + m0 * lda;
    const __half* gB = Bhi + n0 * ldb;

    const int r0 = tid >> 2, s0 = tid & 3;

    float acc[4][8][4];
#pragma unroll
    for (int i = 0; i < 4; i++)
#pragma unroll
        for (int j = 0; j < 8; j++)
#pragma unroll
            for (int r = 0; r < 4; r++) acc[i][j][r] = 0.f;

    const int NC = Kd / 32;

    cp16(smb + r0 * (SKW * 2) + s0 * 16, gA + (long)r0 * lda + s0 * 8);
    cp16(smb + (r0 + 64) * (SKW * 2) + s0 * 16, gA + (long)(r0 + 64) * lda + s0 * 8);
#pragma unroll
    for (int q = 0; q < 4; q++)
        cp16(smb + PLANE_B + (r0 + q * 64) * (SKW * 2) + s0 * 16,
             gB + (long)(r0 + q * 64) * ldb + s0 * 8);
    cp_commit();

    for (int ch = 0; ch < NC; ch++) {
        const int st = ch & 1;
        if (ch + 1 < NC) {
            const int k0 = (ch + 1) * 32;
            const uint32_t sb = smb + (st ^ 1) * STGW;
            cp16(sb + r0 * (SKW * 2) + s0 * 16, gA + (long)r0 * lda + k0 + s0 * 8);
            cp16(sb + (r0 + 64) * (SKW * 2) + s0 * 16, gA + (long)(r0 + 64) * lda + k0 + s0 * 8);
#pragma unroll
            for (int q = 0; q < 4; q++)
                cp16(sb + PLANE_B + (r0 + q * 64) * (SKW * 2) + s0 * 16,
                     gB + (long)(r0 + q * 64) * ldb + k0 + s0 * 8);
            cp_commit();
            cp_wait<1>();
        } else {
            cp_wait<0>();
        }
        __syncthreads();

        const uint32_t* pA = (const uint32_t*)(smem + st * STGW);
        const uint32_t* pB = (const uint32_t*)(smem + st * STGW + PLANE_B);

#pragma unroll
        for (int ks = 0; ks < 2; ks++) {
            const int kb = ks * 16;
            uint32_t af[4][4], bf[8][2];
#pragma unroll
            for (int mt = 0; mt < 4; mt++) {
                const int mr = wm * 64 + mt * 16 + qrow;
                af[mt][0] = pA[(mr * SKW + kb + qk) >> 1];
                af[mt][1] = pA[((mr + 8) * SKW + kb + qk) >> 1];
                af[mt][2] = pA[(mr * SKW + kb + qk + 8) >> 1];
                af[mt][3] = pA[((mr + 8) * SKW + kb + qk + 8) >> 1];
            }
#pragma unroll
            for (int nt = 0; nt < 8; nt++) {
                const int nr = wn * 64 + nt * 8 + qrow;
                bf[nt][0] = pB[(nr * SKW + kb + qk) >> 1];
                bf[nt][1] = pB[(nr * SKW + kb + qk + 8) >> 1];
            }
#pragma unroll
            for (int mt = 0; mt < 4; mt++)
#pragma unroll
                for (int nt = 0; nt < 8; nt++)
                    mma16816(acc[mt][nt], af[mt], bf[nt][0], bf[nt][1]);
        }
        __syncthreads();
    }

    float* cs = (float*)smem;
#pragma unroll
    for (int mt = 0; mt < 4; mt++) {
#pragma unroll
        for (int nt = 0; nt < 8; nt++) {
            const int r = wm * 64 + mt * 16 + qrow;
            const int c = wn * 64 + nt * 8 + (lane & 3) * 2;
            cs[r * 260 + c]           = acc[mt][nt][0];
            cs[r * 260 + c + 1]       = acc[mt][nt][1];
            cs[(r + 8) * 260 + c]     = acc[mt][nt][2];
            cs[(r + 8) * 260 + c + 1] = acc[mt][nt][3];
        }
    }
    __syncthreads();
    {
        const int row = tid >> 1;
        const int hf  = tid & 1;
        const float4* srow = (const float4*)(cs + row * 260 + hf * 128);
        const long cbase = (m0 + row) * (long)ldc + n0 + hf * 128;
        if (EMIT == 0) {
            float4* crow = (float4*)(Cf + cbase);
#pragma unroll
            for (int i = 0; i < 32; i++) crow[i] = srow[i];
        } else {
            __half2* hrow = (__half2*)(Chi + cbase);
            __half2* lrow = (EMIT == 1) ? (__half2*)(Clo + cbase) : nullptr;
#pragma unroll
            for (int i = 0; i < 32; i++) {
                float4 v = srow[i];
                __half hx = __float2half_rn(v.x), hy = __float2half_rn(v.y);
                __half hz = __float2half_rn(v.z), hw = __float2half_rn(v.w);
                hrow[2 * i]     = __halves2half2(hx, hy);
                hrow[2 * i + 1] = __halves2half2(hz, hw);
                if (EMIT == 1) {
                    __half lx = __float2half_rn((v.x - __half2float(hx)) * 64.f);
                    __half ly = __float2half_rn((v.y - __half2float(hy)) * 64.f);
                    __half lz = __float2half_rn((v.z - __half2float(hz)) * 64.f);
                    __half lw = __float2half_rn((v.w - __half2float(hw)) * 64.f);
                    lrow[2 * i]     = __halves2half2(lx, ly);
                    lrow[2 * i + 1] = __halves2half2(lz, lw);
                }
            }
        }
    }
}

// ---------------- score-net stage 2 ----------------
__global__ void score_stage2(const float* __restrict__ hidden,
                             const float* __restrict__ sb1,
                             const float* __restrict__ sw2,
                             const float* __restrict__ sb2,
                             float* __restrict__ out, int nrows)
{
    int warp = (blockIdx.x * blockDim.x + threadIdx.x) >> 5;
    int lane = threadIdx.x & 31;
    if (warp >= nrows) return;
    const float4 hv = ((const float4*)(hidden + (long)warp * 128))[lane];
    const float4 b1 = ((const float4*)sb1)[lane];
    const float4 w2 = ((const float4*)sw2)[lane];
    float s = fmaxf(hv.x + b1.x, 0.f) * w2.x
            + fmaxf(hv.y + b1.y, 0.f) * w2.y
            + fmaxf(hv.z + b1.z, 0.f) * w2.z
            + fmaxf(hv.w + b1.w, 0.f) * w2.w;
#pragma unroll
    for (int o = 16; o > 0; o >>= 1) s += __shfl_xor_sync(0xFFFFFFFFu, s, o);
    if (lane == 0) out[warp] = s + sb2[0];
}

// ---------------- sparsek projection + exact top-128 ----------------
__device__ __forceinline__ unsigned enc_desc(float v) {
    unsigned b = __float_as_uint(v);
    unsigned o = (b & 0x80000000u) ? ~b : (b | 0x80000000u);
    return ~o;
}
__device__ __forceinline__ float dec_desc(unsigned d) {
    unsigned o = ~d;
    unsigned b = (o & 0x80000000u) ? (o ^ 0x80000000u) : ~o;
    return __uint_as_float(b);
}

__global__ __launch_bounds__(1024) void sparsek_topk(const float* __restrict__ scores,
                                                     int* __restrict__ out_idx)
{
    __shared__ unsigned long long key[SS];
    __shared__ unsigned char flag[SS];
    __shared__ float fred[32];
    __shared__ int   ired[32];
    __shared__ int   rho_s, npos_s;
    __shared__ float tau_s;
    int bh  = blockIdx.x;
    int tid = threadIdx.x;
    int lane = tid & 31, warp = tid >> 5;
    const float* s = scores + (long)bh * SS;

    for (int i = tid; i < SS; i += 1024)
        key[i] = ((unsigned long long)enc_desc(s[i]) << 32) | (unsigned)i;
    __syncthreads();

    for (int k = 2; k <= SS; k <<= 1) {
        for (int j = k >> 1; j > 0; j >>= 1) {
            for (int i = tid; i < SS; i += 1024) {
                int ixj = i ^ j;
                if (ixj > i) {
                    bool up = ((i & k) == 0);
                    unsigned long long a = key[i], b = key[ixj];
                    if ((a > b) == up) { key[i] = b; key[ixj] = a; }
                }
            }
            __syncthreads();
        }
    }

    float v[4], pc[4];
#pragma unroll
    for (int j = 0; j < 4; j++) v[j] = dec_desc((unsigned)(key[tid * 4 + j] >> 32));
    pc[0] = v[0]; pc[1] = pc[0] + v[1]; pc[2] = pc[1] + v[2]; pc[3] = pc[2] + v[3];
    float tot = pc[3];
#pragma unroll
    for (int o = 1; o < 32; o <<= 1) {
        float n = __shfl_up_sync(0xFFFFFFFFu, tot, o);
        if (lane >= o) tot += n;
    }
    if (lane == 31) fred[warp] = tot;
    __syncthreads();
    if (warp == 0) {
        float w = fred[lane];
#pragma unroll
        for (int o = 1; o < 32; o <<= 1) {
            float n = __shfl_up_sync(0xFFFFFFFFu, w, o);
            if (lane >= o) w += n;
        }
        fred[lane] = w;
    }
    __syncthreads();
    const float base = (warp ? fred[warp - 1] : 0.f) + (tot - pc[3]);

    int cnt = 0;
#pragma unroll
    for (int j = 0; j < 4; j++) {
        float csj = base + pc[j];
        float thr = (csj - (float)KSEL) / (float)(tid * 4 + j + 1);
        if (v[j] > thr) cnt++;
    }
#pragma unroll
    for (int o = 16; o > 0; o >>= 1) cnt += __shfl_xor_sync(0xFFFFFFFFu, cnt, o);
    if (lane == 0) ired[warp] = cnt;
    __syncthreads();
    if (tid == 0) {
        int r = 0;
#pragma unroll
        for (int i = 0; i < 32; i++) r += ired[i];
        rho_s = (r < 1) ? 1 : r;
    }
    __syncthreads();
    const int rho = rho_s;
    {
        int rr = rho - 1;
        if ((rr >> 2) == tid)
            tau_s = (base + pc[rr & 3] - (float)KSEL) / (float)rho;
    }
    __syncthreads();
    const float tau = tau_s;
    int cnp = 0;
#pragma unroll
    for (int j = 0; j < 4; j++) if (v[j] > tau) cnp++;
#pragma unroll
    for (int o = 16; o > 0; o >>= 1) cnp += __shfl_xor_sync(0xFFFFFFFFu, cnp, o);
    if (lane == 0) ired[warp] = cnp;
    __syncthreads();
    if (tid == 0) {
        int r = 0;
#pragma unroll
        for (int i = 0; i < 32; i++) r += ired[i];
        npos_s = r;
    }
    __syncthreads();

    const int npos = npos_s;
    if (npos >= KSEL) {
        if (tid < KSEL)
            out_idx[bh * KSEL + tid] = (int)(key[tid] & 0xFFFFFFFFu);
    } else {
        if (tid < npos)
            out_idx[bh * KSEL + tid] = (int)(key[tid] & 0xFFFFFFFFu);
        for (int i = tid; i < SS; i += 1024) flag[i] = 0;
        __syncthreads();
        for (int i = tid; i < npos; i += 1024)
            flag[key[i] & 0xFFFFFFFFu] = 1;
        __syncthreads();
        if (tid == 0) {
            int c2 = npos;
            for (int i = 0; i < SS && c2 < KSEL; i++)
                if (!flag[i]) out_idx[bh * KSEL + c2++] = i;
        }
    }
}

// ---------------- gather selected K (hi+lo) and X rows (hi) ----------------
__global__ void gather_kx(const __half* __restrict__ Khi, const __half* __restrict__ Klo,
                          const __half* __restrict__ Xhi,
                          const int* __restrict__ idx,
                          __half* __restrict__ kh, __half* __restrict__ kl,
                          __half* __restrict__ xsel)
{
    int bh = blockIdx.x >> 7;
    int j  = blockIdx.x & 127;
    int t  = threadIdx.x;        // 0..255
    int b  = bh >> 4, h = bh & 15;
    int row = idx[bh * KSEL + j];
    long src = ((long)(b * SS + row)) * HH;
    // copy full X row: 2048 halves = 256 x uint4
    const uint4* xs = (const uint4*)(Xhi + src);
    uint4* xd = (uint4*)(xsel + (long)bh * (KSEL * HH) + (long)j * HH);
    xd[t] = xs[t];
    // copy K head slice: 128 halves = 16 x uint4 per plane
    if (t < 16) {
        const uint4* ks = (const uint4*)(Khi + src + h * HDIM);
        uint4* kd = (uint4*)(kh + (long)bh * (KSEL * HDIM) + (long)j * HDIM);
        kd[t] = ks[t];
    } else if (t < 32) {
        int tt = t - 16;
        const uint4* ks = (const uint4*)(Klo + src + h * HDIM);
        uint4* kd = (uint4*)(kl + (long)bh * (KSEL * HDIM) + (long)j * HDIM);
        kd[tt] = ks[tt];
    }
}

// ---------------- softmax over rows of 128, fp16 hi output ----------------
__global__ void softmax_h(const float* __restrict__ p,
                          __half* __restrict__ phi, int nrows)
{
    int warp = (blockIdx.x * blockDim.x + threadIdx.x) >> 5;
    int lane = threadIdx.x & 31;
    if (warp >= nrows) return;
    float4 v = ((const float4*)(p + (long)warp * 128))[lane];
    float m = fmaxf(fmaxf(v.x, v.y), fmaxf(v.z, v.w));
#pragma unroll
    for (int o = 16; o > 0; o >>= 1) m = fmaxf(m, __shfl_xor_sync(0xFFFFFFFFu, m, o));
    v.x = expf(v.x - m); v.y = expf(v.y - m);
    v.z = expf(v.z - m); v.w = expf(v.w - m);
    float sum = v.x + v.y + v.z + v.w;
#pragma unroll
    for (int o = 16; o > 0; o >>= 1) sum += __shfl_xor_sync(0xFFFFFFFFu, sum, o);
    float inv = 1.0f / sum;
    __half2* ph = (__half2*)(phi + (long)warp * 128 + lane * 4);
    ph[0] = __halves2half2(__float2half_rn(v.x * inv), __float2half_rn(v.y * inv));
    ph[1] = __halves2half2(__float2half_rn(v.z * inv), __float2half_rn(v.w * inv));
}

// ---------------- launch ----------------
extern "C" void kernel_launch(void* const* d_in, const int* in_sizes, int n_in,
                              void* d_out, int out_size)
{
    const float* x   = (const float*)d_in[0];
    const float* wq  = (const float*)d_in[1];
    const float* wk  = (const float*)d_in[2];
    const float* wv  = (const float*)d_in[3];
    const float* wo  = (const float*)d_in[4];
    const float* sw1 = (const float*)d_in[5];
    const float* sb1 = (const float*)d_in[6];
    const float* sw2 = (const float*)d_in[7];
    const float* sb2 = (const float*)d_in[8];
    float* out = (float*)d_out;

    float *pTmp, *pScores;
    int* pIdx;
    __half *pXhi, *pXlo, *pQhi, *pKhi, *pKlo, *pPhi, *pOhi, *pWhi, *pWlo, *pXsel;
    __half *pKselh, *pKsell, *pVselTh, *pVselTl;
    cudaGetSymbolAddress((void**)&pTmp,    gTmp);
    cudaGetSymbolAddress((void**)&pScores, gScores);
    cudaGetSymbolAddress((void**)&pIdx,    gIdx);
    cudaGetSymbolAddress((void**)&pXhi,    gXhi);
    cudaGetSymbolAddress((void**)&pXlo,    gXlo);
    cudaGetSymbolAddress((void**)&pQhi,    gQhi);
    cudaGetSymbolAddress((void**)&pKhi,    gKhi);
    cudaGetSymbolAddress((void**)&pKlo,    gKlo);
    cudaGetSymbolAddress((void**)&pPhi,    gPhi);
    cudaGetSymbolAddress((void**)&pOhi,    gOhi);
    cudaGetSymbolAddress((void**)&pWhi,    gWhi);
    cudaGetSymbolAddress((void**)&pWlo,    gWlo);
    cudaGetSymbolAddress((void**)&pXsel,   gXsel);
    cudaGetSymbolAddress((void**)&pKselh,  gKselh);
    cudaGetSymbolAddress((void**)&pKsell,  gKsell);
    cudaGetSymbolAddress((void**)&pVselTh, gVselTh);
    cudaGetSymbolAddress((void**)&pVselTl, gVselTl);

    const int SM1 = 67584;    // max(2*2*10240, 128*132*4)
    const int SM2 = 67584;    // max(2*3*10240, 128*132*4)
    const int SM3 = 81920;    // 2*4*10240
    const int SMW = 133120;   // max(2*30720, 128*260*4)
    cudaFuncSetAttribute(hgemm_w<0>, cudaFuncAttributeMaxDynamicSharedMemorySize, SMW);
    cudaFuncSetAttribute(hgemm_w<2>, cudaFuncAttributeMaxDynamicSharedMemorySize, SMW);
    cudaFuncSetAttribute(hgemm<1,1>, cudaFuncAttributeMaxDynamicSharedMemorySize, SM1);
    cudaFuncSetAttribute(hgemm<2,0>, cudaFuncAttributeMaxDynamicSharedMemorySize, SM2);
    cudaFuncSetAttribute(hgemm<2,2>, cudaFuncAttributeMaxDynamicSharedMemorySize, SM2);
    cudaFuncSetAttribute(hgemm<3,0>, cudaFuncAttributeMaxDynamicSharedMemorySize, SM3);
    cudaFuncSetAttribute(hgemm<3,1>, cudaFuncAttributeMaxDynamicSharedMemorySize, SM3);

    const long sBH  = (long)SS * HH;
    const long sHd  = HDIM;
    const long sTb  = (long)NHEADS * SS * HDIM;
    const long sTh  = (long)SS * HDIM;
    const long sSelb = (long)KSEL * HDIM * NHEADS;
    const long sSelh = (long)KSEL * HDIM;
    const long sXsb  = (long)NHEADS * KSEL * HH;   // Xsel batch stride
    const long sXsh  = (long)KSEL * HH;            // Xsel head stride

    dim3 gProj(HH / 128, NROWS / 128, 1);   // (16, 64, 1) narrow
    dim3 gProjW(HH / 256, NROWS / 128, 1);  // (8, 64, 1) wide
    dim3 gAtt(1, SS / 128, NBH);            // (1, 32, 32)
    dim3 gVsel(1, 1, NBH);                  // (1, 1, 32)

    // ---- split X (lo needed only for K projection) ----
    split2h<<<(int)((ROWHID + 255) / 256), 256>>>(x, pXhi, pXlo, ROWHID);

    // ---- Q = X @ wq^T (1-prod wide, emit hi only) ----
    split1h<<<(int)((WN + 255) / 256), 256>>>(wq, pWhi, WN);
    hgemm_w<2><<<gProjW, 256, SMW>>>(pXhi, pWhi, nullptr, pQhi, nullptr, HH, HH, HH, HH);
    // ---- K = X @ wk^T (3-prod, protects selection; emit hi+lo) ----
    split2h<<<(int)((WN + 255) / 256), 256>>>(wk, pWhi, pWlo, WN);
    hgemm<3,1><<<gProj, 256, SM3>>>(pXhi, pXlo, pWhi, pWlo, nullptr, pKhi, pKlo,
                                    HH, HH, HH, 0, 0, 0, 0, 0, 0, HH, 1.0f);

    // ---- score-net hidden = K_head @ sw1^T (3-prod batched, fp32 out) ----
    split2h<<<(int)(((long)HDIM * HDIM + 255) / 256), 256>>>(sw1, pWhi, pWlo, (long)HDIM * HDIM);
    hgemm<3,0><<<gAtt, 256, SM3>>>(pKhi, pKlo, pWhi, pWlo, pTmp, nullptr, nullptr,
                                   HH, HDIM, HDIM,
                                   sBH, sHd, 0, 0, sTb, sTh, HDIM, 1.0f);
    score_stage2<<<(NBH * SS) / 8, 256>>>(pTmp, sb1, sw2, sb2, pScores, NBH * SS);
    sparsek_topk<<<NBH, 1024>>>(pScores, pIdx);
    gather_kx<<<NBH * KSEL, 256>>>(pKhi, pKlo, pXhi, pIdx, pKselh, pKsell, pXsel);

    // ---- VselT = wv_head_hi @ Xsel_hi^T (1-prod batched, emit hi+lo) ----
    // C[d, j] per (b,h): exactly the old dense-V values, restricted to selected rows.
    split1h<<<(int)((WN + 255) / 256), 256>>>(wv, pWhi, WN);
    hgemm<1,1><<<gVsel, 256, SM1>>>(pWhi, nullptr, pXsel, nullptr,
                                    nullptr, pVselTh, pVselTl,
                                    HH, HH, KSEL,
                                    0, (long)HDIM * HH,          // A: wv head blocks
                                    sXsb, sXsh,                  // B: Xsel per (b,h)
                                    (long)NHEADS * KSEL * HDIM, sSelh,  // C: VselT
                                    HH, 1.0f);

    // ---- attn scores = Q_head @ Ksel^T * scale (2-prod batched, fp32 out) ----
    const float scale = 0.08838834764831845f;
    hgemm<2,0><<<gAtt, 256, SM2>>>(pQhi, nullptr, pKselh, pKsell, pTmp, nullptr, nullptr,
                                   HH, HDIM, HDIM,
                                   sBH, sHd, sSelb, sSelh, sTb, sTh, HDIM, scale);
    softmax_h<<<(NBH * SS) / 8, 256>>>(pTmp, pPhi, NBH * SS);

    // ---- out_head = P @ Vsel (2-prod batched, emit hi), [B,S,H] layout ----
    hgemm<2,2><<<gAtt, 256, SM2>>>(pPhi, nullptr, pVselTh, pVselTl, nullptr, pOhi, nullptr,
                                   HDIM, KSEL, HH,
                                   sTb, sTh, sSelb, sSelh, sBH, sHd, KSEL, 1.0f);

    // ---- out = O @ wo^T (1-prod wide, fp32 out) ----
    split1h<<<(int)((WN + 255) / 256), 256>>>(wo, pWhi, WN);
    hgemm_w<0><<<gProjW, 256, SMW>>>(pOhi, pWhi, out, nullptr, nullptr, HH, HH, HH, HH);
}

// round 10
// speedup vs baseline: 1.1887x; 1.0092x over previous
#include <cuda_runtime.h>
#include <cuda_fp16.h>
#include <math.h>
#include <stdint.h>

// ---------------- problem constants ----------------
#define BB        2
#define SS        4096
#define HH        2048
#define NHEADS    16
#define HDIM      128
#define KSEL      128
#define NROWS     (BB*SS)            // 8192
#define NBH       (BB*NHEADS)        // 32
#define ROWHID    ((long)NROWS*HH)   // 16777216
#define WN        ((long)HH*HH)      // 4194304
#define SELN      (NBH*KSEL*HDIM)    // 524288
#define XSELN     ((long)NBH*KSEL*HH) // 8388608

// ---------------- scratch (device globals; no allocs allowed) ----------------
__device__ float  gScores[NBH*SS];
__device__ int    gIdx[NBH*KSEL];
__device__ __half gXhi[ROWHID];
__device__ __half gXlo[ROWHID];
__device__ __half gQhi[ROWHID];
__device__ __half gKhi[ROWHID];
__device__ __half gKlo[ROWHID];
__device__ __half gPhi[ROWHID];
__device__ __half gOhi[ROWHID];
__device__ __half gWhi[WN];
__device__ __half gWlo[WN];
__device__ __half gXsel[XSELN];
__device__ __half gKselh[SELN];
__device__ __half gKsell[SELN];
__device__ __half gVselTh[SELN];
__device__ __half gVselTl[SELN];

// =================== helpers ===================
__device__ __forceinline__ uint32_t smem_u32(const void* p) {
    uint32_t a;
    asm("{ .reg .u64 t; cvta.to.shared.u64 t, %1; cvt.u32.u64 %0, t; }" : "=r"(a) : "l"(p));
    return a;
}
__device__ __forceinline__ void cp16(uint32_t dst, const void* src) {
    asm volatile("cp.async.cg.shared.global [%0], [%1], 16;" :: "r"(dst), "l"(src));
}
__device__ __forceinline__ void cp_commit() {
    asm volatile("cp.async.commit_group;" ::: "memory");
}
template<int N>
__device__ __forceinline__ void cp_wait() {
    asm volatile("cp.async.wait_group %0;" :: "n"(N) : "memory");
}
__device__ __forceinline__ void mma16816(float* c, const uint32_t* a, uint32_t b0, uint32_t b1) {
    asm volatile(
        "mma.sync.aligned.m16n8k16.row.col.f32.f16.f16.f32 "
        "{%0,%1,%2,%3}, {%4,%5,%6,%7}, {%8,%9}, {%0,%1,%2,%3};"
        : "+f"(c[0]), "+f"(c[1]), "+f"(c[2]), "+f"(c[3])
        : "r"(a[0]), "r"(a[1]), "r"(a[2]), "r"(a[3]), "r"(b0), "r"(b1));
}

// =================== splits ===================
__global__ void split2h(const float* __restrict__ s, __half* __restrict__ hi,
                        __half* __restrict__ lo, long n)
{
    long i = (long)blockIdx.x * blockDim.x + threadIdx.x;
    if (i >= n) return;
    float x = s[i];
    __half h = __float2half_rn(x);
    hi[i] = h;
    lo[i] = __float2half_rn((x - __half2float(h)) * 64.0f);
}
__global__ void split1h(const float* __restrict__ s, __half* __restrict__ hi, long n)
{
    long i = (long)blockIdx.x * blockDim.x + threadIdx.x;
    if (i >= n) return;
    hi[i] = __float2half_rn(s[i]);
}

#define SKW 40
#define PLANE_B (128 * SKW * 2)      // 10240 bytes
#define PLANE_BW (256 * SKW * 2)     // 20480 bytes (wide B tile)

// =================== HMMA split GEMM (128x128 tile): C = alpha * A * B^T ====
// NPROD==3: C ~= Ahi*Bhi + (Ahi*Blo + Alo*Bhi)/64
// NPROD==2: C ~= Ahi*Bhi + (Ahi*Blo)/64
// NPROD==1: C ~= Ahi*Bhi
// EMIT: 0 = fp32 to Cf; 1 = fp16 hi+lo planes (Chi,Clo); 2 = fp16 hi only;
//       3 = fused score-net stage2: out scalar per row -> Cf[strCb*zb+strCh*zh+m0+row]
//       4 = fused row-softmax, fp16 out -> Chi (ldc row stride)
// Batched via blockIdx.z (zb=z>>4, zh=z&15).
template<int NPROD, int EMIT>
__global__ __launch_bounds__(256, 1) void hgemm(
    const __half* __restrict__ Ahi, const __half* __restrict__ Alo,
    const __half* __restrict__ Bhi, const __half* __restrict__ Blo,
    float* __restrict__ Cf, __half* __restrict__ Chi, __half* __restrict__ Clo,
    int lda, int ldb, int ldc,
    long strAb, long strAh, long strBb, long strBh, long strCb, long strCh,
    int Kd, float alpha,
    const float* __restrict__ sb1g, const float* __restrict__ sw2g,
    const float* __restrict__ sb2g)
{
    constexpr int NPL = (NPROD == 3) ? 4 : (NPROD == 2 ? 3 : 2);
    constexpr int STG = NPL * PLANE_B;
    extern __shared__ char smem[];
    const uint32_t smb = smem_u32(smem);
    const int tid  = threadIdx.x;
    const int wid  = tid >> 5;
    const int lane = tid & 31;
    const int wm   = wid & 1;
    const int wn   = wid >> 1;
    const int qrow = lane >> 2;
    const int qk   = (lane & 3) * 2;

    const int z = blockIdx.z, zb = z >> 4, zh = z & 15;
    const long m0 = (long)blockIdx.y * 128;
    const long n0 = (long)blockIdx.x * 128;

    const __half* pg[4];
    int pld[4];
    pg[0] = Ahi + zb * strAb + zh * strAh + m0 * lda;  pld[0] = lda;
    pg[1] = Bhi + zb * strBb + zh * strBh + n0 * ldb;  pld[1] = ldb;
    pg[2] = (NPROD >= 2) ? (Blo + zb * strBb + zh * strBh + n0 * ldb) : pg[1];
    pld[2] = ldb;
    pg[3] = (NPROD == 3) ? (Alo + zb * strAb + zh * strAh + m0 * lda) : pg[0];
    pld[3] = lda;

    const int r0 = tid >> 2, s0 = tid & 3;
    const int r1 = r0 + 64;

    float acc[4][4][4], axx[4][4][4];
#pragma unroll
    for (int i = 0; i < 4; i++)
#pragma unroll
        for (int j = 0; j < 4; j++)
#pragma unroll
            for (int r = 0; r < 4; r++) { acc[i][j][r] = 0.f; axx[i][j][r] = 0.f; }

    const int NC = Kd / 32;

#pragma unroll
    for (int p = 0; p < NPL; p++) {
        cp16(smb + p * PLANE_B + r0 * (SKW * 2) + s0 * 16, pg[p] + (long)r0 * pld[p] + s0 * 8);
        cp16(smb + p * PLANE_B + r1 * (SKW * 2) + s0 * 16, pg[p] + (long)r1 * pld[p] + s0 * 8);
    }
    cp_commit();

    for (int ch = 0; ch < NC; ch++) {
        const int st = ch & 1;
        if (ch + 1 < NC) {
            const int k0 = (ch + 1) * 32;
            const uint32_t sb = smb + (st ^ 1) * STG;
#pragma unroll
            for (int p = 0; p < NPL; p++) {
                cp16(sb + p * PLANE_B + r0 * (SKW * 2) + s0 * 16, pg[p] + (long)r0 * pld[p] + k0 + s0 * 8);
                cp16(sb + p * PLANE_B + r1 * (SKW * 2) + s0 * 16, pg[p] + (long)r1 * pld[p] + k0 + s0 * 8);
            }
            cp_commit();
            cp_wait<1>();
        } else {
            cp_wait<0>();
        }
        __syncthreads();

        const uint32_t* pAh = (const uint32_t*)(smem + st * STG + 0 * PLANE_B);
        const uint32_t* pBh = (const uint32_t*)(smem + st * STG + 1 * PLANE_B);
        const uint32_t* pBl = (const uint32_t*)(smem + st * STG + 2 * PLANE_B);
        const uint32_t* pAl = (const uint32_t*)(smem + st * STG + 3 * PLANE_B);

#pragma unroll
        for (int ks = 0; ks < 2; ks++) {
            const int kb = ks * 16;
            uint32_t af[4][4], bf[4][2];
#pragma unroll
            for (int mt = 0; mt < 4; mt++) {
                const int mr = wm * 64 + mt * 16 + qrow;
                af[mt][0] = pAh[(mr * SKW + kb + qk) >> 1];
                af[mt][1] = pAh[((mr + 8) * SKW + kb + qk) >> 1];
                af[mt][2] = pAh[(mr * SKW + kb + qk + 8) >> 1];
                af[mt][3] = pAh[((mr + 8) * SKW + kb + qk + 8) >> 1];
            }
#pragma unroll
            for (int nt = 0; nt < 4; nt++) {
                const int nr = wn * 32 + nt * 8 + qrow;
                bf[nt][0] = pBh[(nr * SKW + kb + qk) >> 1];
                bf[nt][1] = pBh[(nr * SKW + kb + qk + 8) >> 1];
            }
#pragma unroll
            for (int mt = 0; mt < 4; mt++)
#pragma unroll
                for (int nt = 0; nt < 4; nt++)
                    mma16816(acc[mt][nt], af[mt], bf[nt][0], bf[nt][1]);
            if (NPROD >= 2) {
                uint32_t bl[4][2];
#pragma unroll
                for (int nt = 0; nt < 4; nt++) {
                    const int nr = wn * 32 + nt * 8 + qrow;
                    bl[nt][0] = pBl[(nr * SKW + kb + qk) >> 1];
                    bl[nt][1] = pBl[(nr * SKW + kb + qk + 8) >> 1];
                }
#pragma unroll
                for (int mt = 0; mt < 4; mt++)
#pragma unroll
                    for (int nt = 0; nt < 4; nt++)
                        mma16816(axx[mt][nt], af[mt], bl[nt][0], bl[nt][1]);
            }
            if (NPROD == 3) {
#pragma unroll
                for (int mt = 0; mt < 4; mt++) {
                    const int mr = wm * 64 + mt * 16 + qrow;
                    af[mt][0] = pAl[(mr * SKW + kb + qk) >> 1];
                    af[mt][1] = pAl[((mr + 8) * SKW + kb + qk) >> 1];
                    af[mt][2] = pAl[(mr * SKW + kb + qk + 8) >> 1];
                    af[mt][3] = pAl[((mr + 8) * SKW + kb + qk + 8) >> 1];
                }
#pragma unroll
                for (int mt = 0; mt < 4; mt++)
#pragma unroll
                    for (int nt = 0; nt < 4; nt++)
                        mma16816(axx[mt][nt], af[mt], bf[nt][0], bf[nt][1]);
            }
        }
        __syncthreads();
    }

    // ---- stage fp32 tile in smem ----
    float* cs = (float*)smem;   // [128][132]
    float* sb1s = (float*)(smem + 128 * 132 * 4);          // EMIT==3 extras
    float* sw2s = sb1s + 128;
    const float inv64 = 1.0f / 64.0f;
#pragma unroll
    for (int mt = 0; mt < 4; mt++) {
#pragma unroll
        for (int nt = 0; nt < 4; nt++) {
            const int r = wm * 64 + mt * 16 + qrow;
            const int c = wn * 32 + nt * 8 + (lane & 3) * 2;
            if (NPROD >= 2) {
                cs[r * 132 + c]           = alpha * (acc[mt][nt][0] + axx[mt][nt][0] * inv64);
                cs[r * 132 + c + 1]       = alpha * (acc[mt][nt][1] + axx[mt][nt][1] * inv64);
                cs[(r + 8) * 132 + c]     = alpha * (acc[mt][nt][2] + axx[mt][nt][2] * inv64);
                cs[(r + 8) * 132 + c + 1] = alpha * (acc[mt][nt][3] + axx[mt][nt][3] * inv64);
            } else {
                cs[r * 132 + c]           = alpha * acc[mt][nt][0];
                cs[r * 132 + c + 1]       = alpha * acc[mt][nt][1];
                cs[(r + 8) * 132 + c]     = alpha * acc[mt][nt][2];
                cs[(r + 8) * 132 + c + 1] = alpha * acc[mt][nt][3];
            }
        }
    }
    if (EMIT == 3) {
        if (tid < 128) sb1s[tid] = sb1g[tid];
        else           sw2s[tid - 128] = sw2g[tid - 128];
    }
    __syncthreads();

    const int row = tid >> 1;
    const int hf  = tid & 1;
    if (EMIT == 3) {
        // fused score-net stage 2: s = sum relu(h + sb1) * sw2  (+ sb2)
        const float* crow = cs + row * 132 + hf * 64;
        float s = 0.f;
#pragma unroll
        for (int i = 0; i < 64; i++)
            s += fmaxf(crow[i] + sb1s[hf * 64 + i], 0.f) * sw2s[hf * 64 + i];
        s += __shfl_xor_sync(0xFFFFFFFFu, s, 1);
        if (hf == 0)
            Cf[zb * strCb + zh * strCh + m0 + row] = s + sb2g[0];
    } else if (EMIT == 4) {
        // fused row softmax -> fp16
        float* crow = cs + row * 132 + hf * 64;
        float m = -1e30f;
#pragma unroll
        for (int i = 0; i < 64; i++) m = fmaxf(m, crow[i]);
        m = fmaxf(m, __shfl_xor_sync(0xFFFFFFFFu, m, 1));
        float sum = 0.f;
#pragma unroll
        for (int i = 0; i < 64; i++) {
            float e = expf(crow[i] - m);
            crow[i] = e;
            sum += e;
        }
        sum += __shfl_xor_sync(0xFFFFFFFFu, sum, 1);
        const float inv = 1.0f / sum;
        __half2* ph = (__half2*)(Chi + zb * strCb + zh * strCh + (m0 + row) * (long)ldc + hf * 64);
#pragma unroll
        for (int i = 0; i < 16; i++) {
            float4 v = ((const float4*)crow)[i];
            ph[2 * i]     = __halves2half2(__float2half_rn(v.x * inv), __float2half_rn(v.y * inv));
            ph[2 * i + 1] = __halves2half2(__float2half_rn(v.z * inv), __float2half_rn(v.w * inv));
        }
    } else {
        const float4* srow = (const float4*)(cs + row * 132 + hf * 64);
        const long cbase = zb * strCb + zh * strCh + (m0 + row) * (long)ldc + n0 + hf * 64;
        if (EMIT == 0) {
            float4* crow = (float4*)(Cf + cbase);
#pragma unroll
            for (int i = 0; i < 16; i++) crow[i] = srow[i];
        } else {
            __half2* hrow = (__half2*)(Chi + cbase);
            __half2* lrow = (EMIT == 1) ? (__half2*)(Clo + cbase) : nullptr;
#pragma unroll
            for (int i = 0; i < 16; i++) {
                float4 v = srow[i];
                __half hx = __float2half_rn(v.x), hy = __float2half_rn(v.y);
                __half hz = __float2half_rn(v.z), hw = __float2half_rn(v.w);
                hrow[2 * i]     = __halves2half2(hx, hy);
                hrow[2 * i + 1] = __halves2half2(hz, hw);
                if (EMIT == 1) {
                    __half lx = __float2half_rn((v.x - __half2float(hx)) * 64.f);
                    __half ly = __float2half_rn((v.y - __half2float(hy)) * 64.f);
                    __half lz = __float2half_rn((v.z - __half2float(hz)) * 64.f);
                    __half lw = __float2half_rn((v.w - __half2float(hw)) * 64.f);
                    lrow[2 * i]     = __halves2half2(lx, ly);
                    lrow[2 * i + 1] = __halves2half2(lz, lw);
                }
            }
        }
    }
}

// =================== WIDE 1-prod HMMA GEMM (128x256 tile): C = A * B^T =====
#define STGW (PLANE_B + PLANE_BW)    // 30720 per stage

template<int EMIT>
__global__ __launch_bounds__(256, 1) void hgemm_w(
    const __half* __restrict__ Ahi, const __half* __restrict__ Bhi,
    float* __restrict__ Cf, __half* __restrict__ Chi, __half* __restrict__ Clo,
    int lda, int ldb, int ldc, int Kd)
{
    extern __shared__ char smem[];
    const uint32_t smb = smem_u32(smem);
    const int tid  = threadIdx.x;
    const int wid  = tid >> 5;
    const int lane = tid & 31;
    const int wm   = wid & 1;
    const int wn   = wid >> 1;
    const int qrow = lane >> 2;
    const int qk   = (lane & 3) * 2;

    const long m0 = (long)blockIdx.y * 128;
    const long n0 = (long)blockIdx.x * 256;

    const __half* gA = Ahi + m0 * lda;
    const __half* gB = Bhi + n0 * ldb;

    const int r0 = tid >> 2, s0 = tid & 3;

    float acc[4][8][4];
#pragma unroll
    for (int i = 0; i < 4; i++)
#pragma unroll
        for (int j = 0; j < 8; j++)
#pragma unroll
            for (int r = 0; r < 4; r++) acc[i][j][r] = 0.f;

    const int NC = Kd / 32;

    cp16(smb + r0 * (SKW * 2) + s0 * 16, gA + (long)r0 * lda + s0 * 8);
    cp16(smb + (r0 + 64) * (SKW * 2) + s0 * 16, gA + (long)(r0 + 64) * lda + s0 * 8);
#pragma unroll
    for (int q = 0; q < 4; q++)
        cp16(smb + PLANE_B + (r0 + q * 64) * (SKW * 2) + s0 * 16,
             gB + (long)(r0 + q * 64) * ldb + s0 * 8);
    cp_commit();

    for (int ch = 0; ch < NC; ch++) {
        const int st = ch & 1;
        if (ch + 1 < NC) {
            const int k0 = (ch + 1) * 32;
            const uint32_t sb = smb + (st ^ 1) * STGW;
            cp16(sb + r0 * (SKW * 2) + s0 * 16, gA + (long)r0 * lda + k0 + s0 * 8);
            cp16(sb + (r0 + 64) * (SKW * 2) + s0 * 16, gA + (long)(r0 + 64) * lda + k0 + s0 * 8);
#pragma unroll
            for (int q = 0; q < 4; q++)
                cp16(sb + PLANE_B + (r0 + q * 64) * (SKW * 2) + s0 * 16,
                     gB + (long)(r0 + q * 64) * ldb + k0 + s0 * 8);
            cp_commit();
            cp_wait<1>();
        } else {
            cp_wait<0>();
        }
        __syncthreads();

        const uint32_t* pA = (const uint32_t*)(smem + st * STGW);
        const uint32_t* pB = (const uint32_t*)(smem + st * STGW + PLANE_B);

#pragma unroll
        for (int ks = 0; ks < 2; ks++) {
            const int kb = ks * 16;
            uint32_t af[4][4], bf[8][2];
#pragma unroll
            for (int mt = 0; mt < 4; mt++) {
                const int mr = wm * 64 + mt * 16 + qrow;
                af[mt][0] = pA[(mr * SKW + kb + qk) >> 1];
                af[mt][1] = pA[((mr + 8) * SKW + kb + qk) >> 1];
                af[mt][2] = pA[(mr * SKW + kb + qk + 8) >> 1];
                af[mt][3] = pA[((mr + 8) * SKW + kb + qk + 8) >> 1];
            }
#pragma unroll
            for (int nt = 0; nt < 8; nt++) {
                const int nr = wn * 64 + nt * 8 + qrow;
                bf[nt][0] = pB[(nr * SKW + kb + qk) >> 1];
                bf[nt][1] = pB[(nr * SKW + kb + qk + 8) >> 1];
            }
#pragma unroll
            for (int mt = 0; mt < 4; mt++)
#pragma unroll
                for (int nt = 0; nt < 8; nt++)
                    mma16816(acc[mt][nt], af[mt], bf[nt][0], bf[nt][1]);
        }
        __syncthreads();
    }

    float* cs = (float*)smem;
#pragma unroll
    for (int mt = 0; mt < 4; mt++) {
#pragma unroll
        for (int nt = 0; nt < 8; nt++) {
            const int r = wm * 64 + mt * 16 + qrow;
            const int c = wn * 64 + nt * 8 + (lane & 3) * 2;
            cs[r * 260 + c]           = acc[mt][nt][0];
            cs[r * 260 + c + 1]       = acc[mt][nt][1];
            cs[(r + 8) * 260 + c]     = acc[mt][nt][2];
            cs[(r + 8) * 260 + c + 1] = acc[mt][nt][3];
        }
    }
    __syncthreads();
    {
        const int row = tid >> 1;
        const int hf  = tid & 1;
        const float4* srow = (const float4*)(cs + row * 260 + hf * 128);
        const long cbase = (m0 + row) * (long)ldc + n0 + hf * 128;
        if (EMIT == 0) {
            float4* crow = (float4*)(Cf + cbase);
#pragma unroll
            for (int i = 0; i < 32; i++) crow[i] = srow[i];
        } else {
            __half2* hrow = (__half2*)(Chi + cbase);
            __half2* lrow = (EMIT == 1) ? (__half2*)(Clo + cbase) : nullptr;
#pragma unroll
            for (int i = 0; i < 32; i++) {
                float4 v = srow[i];
                __half hx = __float2half_rn(v.x), hy = __float2half_rn(v.y);
                __half hz = __float2half_rn(v.z), hw = __float2half_rn(v.w);
                hrow[2 * i]     = __halves2half2(hx, hy);
                hrow[2 * i + 1] = __halves2half2(hz, hw);
                if (EMIT == 1) {
                    __half lx = __float2half_rn((v.x - __half2float(hx)) * 64.f);
                    __half ly = __float2half_rn((v.y - __half2float(hy)) * 64.f);
                    __half lz = __float2half_rn((v.z - __half2float(hz)) * 64.f);
                    __half lw = __float2half_rn((v.w - __half2float(hw)) * 64.f);
                    lrow[2 * i]     = __halves2half2(lx, ly);
                    lrow[2 * i + 1] = __halves2half2(lz, lw);
                }
            }
        }
    }
}

// ---------------- sparsek projection + exact top-128 ----------------
__device__ __forceinline__ unsigned enc_desc(float v) {
    unsigned b = __float_as_uint(v);
    unsigned o = (b & 0x80000000u) ? ~b : (b | 0x80000000u);
    return ~o;
}
__device__ __forceinline__ float dec_desc(unsigned d) {
    unsigned o = ~d;
    unsigned b = (o & 0x80000000u) ? (o ^ 0x80000000u) : ~o;
    return __uint_as_float(b);
}

__global__ __launch_bounds__(1024) void sparsek_topk(const float* __restrict__ scores,
                                                     int* __restrict__ out_idx)
{
    __shared__ unsigned long long key[SS];
    __shared__ unsigned char flag[SS];
    __shared__ float fred[32];
    __shared__ int   ired[32];
    __shared__ int   rho_s, npos_s;
    __shared__ float tau_s;
    int bh  = blockIdx.x;
    int tid = threadIdx.x;
    int lane = tid & 31, warp = tid >> 5;
    const float* s = scores + (long)bh * SS;

    for (int i = tid; i < SS; i += 1024)
        key[i] = ((unsigned long long)enc_desc(s[i]) << 32) | (unsigned)i;
    __syncthreads();

    for (int k = 2; k <= SS; k <<= 1) {
        for (int j = k >> 1; j > 0; j >>= 1) {
            for (int i = tid; i < SS; i += 1024) {
                int ixj = i ^ j;
                if (ixj > i) {
                    bool up = ((i & k) == 0);
                    unsigned long long a = key[i], b = key[ixj];
                    if ((a > b) == up) { key[i] = b; key[ixj] = a; }
                }
            }
            __syncthreads();
        }
    }

    float v[4], pc[4];
#pragma unroll
    for (int j = 0; j < 4; j++) v[j] = dec_desc((unsigned)(key[tid * 4 + j] >> 32));
    pc[0] = v[0]; pc[1] = pc[0] + v[1]; pc[2] = pc[1] + v[2]; pc[3] = pc[2] + v[3];
    float tot = pc[3];
#pragma unroll
    for (int o = 1; o < 32; o <<= 1) {
        float n = __shfl_up_sync(0xFFFFFFFFu, tot, o);
        if (lane >= o) tot += n;
    }
    if (lane == 31) fred[warp] = tot;
    __syncthreads();
    if (warp == 0) {
        float w = fred[lane];
#pragma unroll
        for (int o = 1; o < 32; o <<= 1) {
            float n = __shfl_up_sync(0xFFFFFFFFu, w, o);
            if (lane >= o) w += n;
        }
        fred[lane] = w;
    }
    __syncthreads();
    const float base = (warp ? fred[warp - 1] : 0.f) + (tot - pc[3]);

    int cnt = 0;
#pragma unroll
    for (int j = 0; j < 4; j++) {
        float csj = base + pc[j];
        float thr = (csj - (float)KSEL) / (float)(tid * 4 + j + 1);
        if (v[j] > thr) cnt++;
    }
#pragma unroll
    for (int o = 16; o > 0; o >>= 1) cnt += __shfl_xor_sync(0xFFFFFFFFu, cnt, o);
    if (lane == 0) ired[warp] = cnt;
    __syncthreads();
    if (tid == 0) {
        int r = 0;
#pragma unroll
        for (int i = 0; i < 32; i++) r += ired[i];
        rho_s = (r < 1) ? 1 : r;
    }
    __syncthreads();
    const int rho = rho_s;
    {
        int rr = rho - 1;
        if ((rr >> 2) == tid)
            tau_s = (base + pc[rr & 3] - (float)KSEL) / (float)rho;
    }
    __syncthreads();
    const float tau = tau_s;
    int cnp = 0;
#pragma unroll
    for (int j = 0; j < 4; j++) if (v[j] > tau) cnp++;
#pragma unroll
    for (int o = 16; o > 0; o >>= 1) cnp += __shfl_xor_sync(0xFFFFFFFFu, cnp, o);
    if (lane == 0) ired[warp] = cnp;
    __syncthreads();
    if (tid == 0) {
        int r = 0;
#pragma unroll
        for (int i = 0; i < 32; i++) r += ired[i];
        npos_s = r;
    }
    __syncthreads();

    const int npos = npos_s;
    if (npos >= KSEL) {
        if (tid < KSEL)
            out_idx[bh * KSEL + tid] = (int)(key[tid] & 0xFFFFFFFFu);
    } else {
        if (tid < npos)
            out_idx[bh * KSEL + tid] = (int)(key[tid] & 0xFFFFFFFFu);
        for (int i = tid; i < SS; i += 1024) flag[i] = 0;
        __syncthreads();
        for (int i = tid; i < npos; i += 1024)
            flag[key[i] & 0xFFFFFFFFu] = 1;
        __syncthreads();
        if (tid == 0) {
            int c2 = npos;
            for (int i = 0; i < SS && c2 < KSEL; i++)
                if (!flag[i]) out_idx[bh * KSEL + c2++] = i;
        }
    }
}

// ---------------- gather selected K (hi+lo) and X rows (hi) ----------------
__global__ void gather_kx(const __half* __restrict__ Khi, const __half* __restrict__ Klo,
                          const __half* __restrict__ Xhi,
                          const int* __restrict__ idx,
                          __half* __restrict__ kh, __half* __restrict__ kl,
                          __half* __restrict__ xsel)
{
    int bh = blockIdx.x >> 7;
    int j  = blockIdx.x & 127;
    int t  = threadIdx.x;        // 0..255
    int b  = bh >> 4, h = bh & 15;
    int row = idx[bh * KSEL + j];
    long src = ((long)(b * SS + row)) * HH;
    const uint4* xs = (const uint4*)(Xhi + src);
    uint4* xd = (uint4*)(xsel + (long)bh * (KSEL * HH) + (long)j * HH);
    xd[t] = xs[t];
    if (t < 16) {
        const uint4* ks = (const uint4*)(Khi + src + h * HDIM);
        uint4* kd = (uint4*)(kh + (long)bh * (KSEL * HDIM) + (long)j * HDIM);
        kd[t] = ks[t];
    } else if (t < 32) {
        int tt = t - 16;
        const uint4* ks = (const uint4*)(Klo + src + h * HDIM);
        uint4* kd = (uint4*)(kl + (long)bh * (KSEL * HDIM) + (long)j * HDIM);
        kd[tt] = ks[tt];
    }
}

// ---------------- launch ----------------
extern "C" void kernel_launch(void* const* d_in, const int* in_sizes, int n_in,
                              void* d_out, int out_size)
{
    const float* x   = (const float*)d_in[0];
    const float* wq  = (const float*)d_in[1];
    const float* wk  = (const float*)d_in[2];
    const float* wv  = (const float*)d_in[3];
    const float* wo  = (const float*)d_in[4];
    const float* sw1 = (const float*)d_in[5];
    const float* sb1 = (const float*)d_in[6];
    const float* sw2 = (const float*)d_in[7];
    const float* sb2 = (const float*)d_in[8];
    float* out = (float*)d_out;

    float *pScores;
    int* pIdx;
    __half *pXhi, *pXlo, *pQhi, *pKhi, *pKlo, *pPhi, *pOhi, *pWhi, *pWlo, *pXsel;
    __half *pKselh, *pKsell, *pVselTh, *pVselTl;
    cudaGetSymbolAddress((void**)&pScores, gScores);
    cudaGetSymbolAddress((void**)&pIdx,    gIdx);
    cudaGetSymbolAddress((void**)&pXhi,    gXhi);
    cudaGetSymbolAddress((void**)&pXlo,    gXlo);
    cudaGetSymbolAddress((void**)&pQhi,    gQhi);
    cudaGetSymbolAddress((void**)&pKhi,    gKhi);
    cudaGetSymbolAddress((void**)&pKlo,    gKlo);
    cudaGetSymbolAddress((void**)&pPhi,    gPhi);
    cudaGetSymbolAddress((void**)&pOhi,    gOhi);
    cudaGetSymbolAddress((void**)&pWhi,    gWhi);
    cudaGetSymbolAddress((void**)&pWlo,    gWlo);
    cudaGetSymbolAddress((void**)&pXsel,   gXsel);
    cudaGetSymbolAddress((void**)&pKselh,  gKselh);
    cudaGetSymbolAddress((void**)&pKsell,  gKsell);
    cudaGetSymbolAddress((void**)&pVselTh, gVselTh);
    cudaGetSymbolAddress((void**)&pVselTl, gVselTl);

    const int SM1 = 67584;    // max(2*2*10240, 128*132*4)
    const int SM2 = 67584;
    const int SM3 = 81920;    // 2*4*10240  (also covers cs + sb1/sw2 stash: 68608)
    const int SMW = 133120;   // max(2*30720, 128*260*4)
    cudaFuncSetAttribute(hgemm_w<0>, cudaFuncAttributeMaxDynamicSharedMemorySize, SMW);
    cudaFuncSetAttribute(hgemm_w<2>, cudaFuncAttributeMaxDynamicSharedMemorySize, SMW);
    cudaFuncSetAttribute(hgemm<1,1>, cudaFuncAttributeMaxDynamicSharedMemorySize, SM1);
    cudaFuncSetAttribute(hgemm<2,2>, cudaFuncAttributeMaxDynamicSharedMemorySize, SM2);
    cudaFuncSetAttribute(hgemm<2,4>, cudaFuncAttributeMaxDynamicSharedMemorySize, SM2);
    cudaFuncSetAttribute(hgemm<3,1>, cudaFuncAttributeMaxDynamicSharedMemorySize, SM3);
    cudaFuncSetAttribute(hgemm<3,3>, cudaFuncAttributeMaxDynamicSharedMemorySize, SM3);

    const long sBH  = (long)SS * HH;
    const long sHd  = HDIM;
    const long sTb  = (long)NHEADS * SS * HDIM;
    const long sTh  = (long)SS * HDIM;
    const long sSelb = (long)KSEL * HDIM * NHEADS;
    const long sSelh = (long)KSEL * HDIM;
    const long sXsb  = (long)NHEADS * KSEL * HH;
    const long sXsh  = (long)KSEL * HH;
    const long sScb  = (long)NHEADS * SS;   // scores batch stride
    const long sSch  = (long)SS;            // scores head stride

    dim3 gProj(HH / 128, NROWS / 128, 1);   // (16, 64, 1) narrow
    dim3 gProjW(HH / 256, NROWS / 128, 1);  // (8, 64, 1) wide
    dim3 gAtt(1, SS / 128, NBH);            // (1, 32, 32)
    dim3 gVsel(1, 1, NBH);                  // (1, 1, 32)

    // ---- split X (lo needed only for K projection) ----
    split2h<<<(int)((ROWHID + 255) / 256), 256>>>(x, pXhi, pXlo, ROWHID);

    // ---- Q = X @ wq^T (1-prod wide, emit hi only) ----
    split1h<<<(int)((WN + 255) / 256), 256>>>(wq, pWhi, WN);
    hgemm_w<2><<<gProjW, 256, SMW>>>(pXhi, pWhi, nullptr, pQhi, nullptr, HH, HH, HH, HH);
    // ---- K = X @ wk^T (3-prod, protects selection; emit hi+lo) ----
    split2h<<<(int)((WN + 255) / 256), 256>>>(wk, pWhi, pWlo, WN);
    hgemm<3,1><<<gProj, 256, SM3>>>(pXhi, pXlo, pWhi, pWlo, nullptr, pKhi, pKlo,
                                    HH, HH, HH, 0, 0, 0, 0, 0, 0, HH, 1.0f,
                                    nullptr, nullptr, nullptr);

    // ---- kv_scores: hidden GEMM (3-prod) fused with relu-dot score head ----
    split2h<<<(int)(((long)HDIM * HDIM + 255) / 256), 256>>>(sw1, pWhi, pWlo, (long)HDIM * HDIM);
    hgemm<3,3><<<gAtt, 256, SM3>>>(pKhi, pKlo, pWhi, pWlo, pScores, nullptr, nullptr,
                                   HH, HDIM, 1,
                                   sBH, sHd, 0, 0, sScb, sSch, HDIM, 1.0f,
                                   sb1, sw2, sb2);
    sparsek_topk<<<NBH, 1024>>>(pScores, pIdx);
    gather_kx<<<NBH * KSEL, 256>>>(pKhi, pKlo, pXhi, pIdx, pKselh, pKsell, pXsel);

    // ---- VselT = wv_head_hi @ Xsel_hi^T (1-prod batched, emit hi+lo) ----
    split1h<<<(int)((WN + 255) / 256), 256>>>(wv, pWhi, WN);
    hgemm<1,1><<<gVsel, 256, SM1>>>(pWhi, nullptr, pXsel, nullptr,
                                    nullptr, pVselTh, pVselTl,
                                    HH, HH, KSEL,
                                    0, (long)HDIM * HH,
                                    sXsb, sXsh,
                                    (long)NHEADS * KSEL * HDIM, sSelh,
                                    HH, 1.0f, nullptr, nullptr, nullptr);

    // ---- P = softmax(Q_head @ Ksel^T * scale)  (2-prod, fused softmax, fp16) ----
    const float scale = 0.08838834764831845f;
    hgemm<2,4><<<gAtt, 256, SM2>>>(pQhi, nullptr, pKselh, pKsell, nullptr, pPhi, nullptr,
                                   HH, HDIM, HDIM,
                                   sBH, sHd, sSelb, sSelh, sTb, sTh, HDIM, scale,
                                   nullptr, nullptr, nullptr);

    // ---- out_head = P @ Vsel (2-prod batched, emit hi), [B,S,H] layout ----
    hgemm<2,2><<<gAtt, 256, SM2>>>(pPhi, nullptr, pVselTh, pVselTl, nullptr, pOhi, nullptr,
                                   HDIM, KSEL, HH,
                                   sTb, sTh, sSelb, sSelh, sBH, sHd, KSEL, 1.0f,
                                   nullptr, nullptr, nullptr);

    // ---- out = O @ wo^T (1-prod wide, fp32 out) ----
    split1h<<<(int)((WN + 255) / 256), 256>>>(wo, pWhi, WN);
    hgemm_w<0><<<gProjW, 256, SMW>>>(pOhi, pWhi, out, nullptr, nullptr, HH, HH, HH, HH);
}

// round 11
// speedup vs baseline: 1.2273x; 1.0325x over previous
#include <cuda_runtime.h>
#include <cuda_fp16.h>
#include <math.h>
#include <stdint.h>

// ---------------- problem constants ----------------
#define BB        2
#define SS        4096
#define HH        2048
#define NHEADS    16
#define HDIM      128
#define KSEL      128
#define NROWS     (BB*SS)            // 8192
#define NBH       (BB*NHEADS)        // 32
#define ROWHID    ((long)NROWS*HH)   // 16777216
#define WN        ((long)HH*HH)      // 4194304
#define SW1N      ((long)HDIM*HDIM)  // 16384
#define SELN      (NBH*KSEL*HDIM)    // 524288
#define XSELN     ((long)NBH*KSEL*HH) // 8388608

// ---------------- scratch (device globals; no allocs allowed) ----------------
__device__ float  gScores[NBH*SS];
__device__ int    gIdx[NBH*KSEL];
__device__ __half gXhi[ROWHID];
__device__ __half gXlo[ROWHID];
__device__ __half gQhi[ROWHID];
__device__ __half gKhi[ROWHID];
__device__ __half gKlo[ROWHID];
__device__ __half gPhi[ROWHID];
__device__ __half gOhi[ROWHID];
__device__ __half gWq[WN];
__device__ __half gWkhi[WN];
__device__ __half gWklo[WN];
__device__ __half gWv[WN];
__device__ __half gWo[WN];
__device__ __half gSw1hi[SW1N];
__device__ __half gSw1lo[SW1N];
__device__ __half gXsel[XSELN];
__device__ __half gKselh[SELN];
__device__ __half gKsell[SELN];
__device__ __half gVselTh[SELN];
__device__ __half gVselTl[SELN];

// =================== helpers ===================
__device__ __forceinline__ uint32_t smem_u32(const void* p) {
    uint32_t a;
    asm("{ .reg .u64 t; cvta.to.shared.u64 t, %1; cvt.u32.u64 %0, t; }" : "=r"(a) : "l"(p));
    return a;
}
__device__ __forceinline__ void cp16(uint32_t dst, const void* src) {
    asm volatile("cp.async.cg.shared.global [%0], [%1], 16;" :: "r"(dst), "l"(src));
}
__device__ __forceinline__ void cp_commit() {
    asm volatile("cp.async.commit_group;" ::: "memory");
}
template<int N>
__device__ __forceinline__ void cp_wait() {
    asm volatile("cp.async.wait_group %0;" :: "n"(N) : "memory");
}
__device__ __forceinline__ void mma16816(float* c, const uint32_t* a, uint32_t b0, uint32_t b1) {
    asm volatile(
        "mma.sync.aligned.m16n8k16.row.col.f32.f16.f16.f32 "
        "{%0,%1,%2,%3}, {%4,%5,%6,%7}, {%8,%9}, {%0,%1,%2,%3};"
        : "+f"(c[0]), "+f"(c[1]), "+f"(c[2]), "+f"(c[3])
        : "r"(a[0]), "r"(a[1]), "r"(a[2]), "r"(a[3]), "r"(b0), "r"(b1));
}

// =================== vectorized splits (8 elems / thread) ===================
__device__ __forceinline__ void cvt1x8(const float* __restrict__ s, __half* __restrict__ d, long g) {
    const float4* sp = (const float4*)s + g * 2;
    float4 a = sp[0], b = sp[1];
    __half2 h0 = __halves2half2(__float2half_rn(a.x), __float2half_rn(a.y));
    __half2 h1 = __halves2half2(__float2half_rn(a.z), __float2half_rn(a.w));
    __half2 h2 = __halves2half2(__float2half_rn(b.x), __float2half_rn(b.y));
    __half2 h3 = __halves2half2(__float2half_rn(b.z), __float2half_rn(b.w));
    uint4 o;
    o.x = *(uint32_t*)&h0; o.y = *(uint32_t*)&h1;
    o.z = *(uint32_t*)&h2; o.w = *(uint32_t*)&h3;
    ((uint4*)d)[g] = o;
}
__device__ __forceinline__ void cvt2x8(const float* __restrict__ s,
                                       __half* __restrict__ dh, __half* __restrict__ dl, long g) {
    const float4* sp = (const float4*)s + g * 2;
    float4 a = sp[0], b = sp[1];
    float f[8] = {a.x, a.y, a.z, a.w, b.x, b.y, b.z, b.w};
    uint32_t hw[4], lw[4];
#pragma unroll
    for (int j = 0; j < 4; j++) {
        __half h0 = __float2half_rn(f[2 * j]);
        __half h1 = __float2half_rn(f[2 * j + 1]);
        __half l0 = __float2half_rn((f[2 * j] - __half2float(h0)) * 64.0f);
        __half l1 = __float2half_rn((f[2 * j + 1] - __half2float(h1)) * 64.0f);
        __half2 hh = __halves2half2(h0, h1);
        __half2 ll = __halves2half2(l0, l1);
        hw[j] = *(uint32_t*)&hh;
        lw[j] = *(uint32_t*)&ll;
    }
    ((uint4*)dh)[g] = make_uint4(hw[0], hw[1], hw[2], hw[3]);
    ((uint4*)dl)[g] = make_uint4(lw[0], lw[1], lw[2], lw[3]);
}

// split X: hi + lo, 8 elems/thread
__global__ void splitX(const float* __restrict__ s, __half* __restrict__ hi,
                       __half* __restrict__ lo, long n8)
{
    long i = (long)blockIdx.x * blockDim.x + threadIdx.x;
    if (i >= n8) return;
    cvt2x8(s, hi, lo, i);
}

// split ALL weights in one launch: wq/wv/wo hi-only, wk + sw1 hi+lo
__global__ void splitW(const float* __restrict__ wq, const float* __restrict__ wk,
                       const float* __restrict__ wv, const float* __restrict__ wo,
                       const float* __restrict__ sw1,
                       __half* __restrict__ q, __half* __restrict__ khi, __half* __restrict__ klo,
                       __half* __restrict__ v, __half* __restrict__ o,
                       __half* __restrict__ s1hi, __half* __restrict__ s1lo)
{
    long i = (long)blockIdx.x * blockDim.x + threadIdx.x;
    if (i >= WN / 8) return;
    cvt1x8(wq, q, i);
    cvt2x8(wk, khi, klo, i);
    cvt1x8(wv, v, i);
    cvt1x8(wo, o, i);
    if (i < SW1N / 8) cvt2x8(sw1, s1hi, s1lo, i);
}

#define SKW 40
#define PLANE_B (128 * SKW * 2)      // 10240 bytes
#define PLANE_BW (256 * SKW * 2)     // 20480 bytes (wide B tile)

// =================== HMMA split GEMM (128x128 tile): C = alpha * A * B^T ====
// NPROD==3: C ~= Ahi*Bhi + (Ahi*Blo + Alo*Bhi)/64
// NPROD==2: C ~= Ahi*Bhi + (Ahi*Blo)/64
// NPROD==1: C ~= Ahi*Bhi
// EMIT: 0 = fp32 to Cf; 1 = fp16 hi+lo planes (Chi,Clo); 2 = fp16 hi only;
//       3 = fused score-net stage2; 4 = fused row-softmax fp16.
// Batched via blockIdx.z (zb=z>>4, zh=z&15).
template<int NPROD, int EMIT>
__global__ __launch_bounds__(256, 1) void hgemm(
    const __half* __restrict__ Ahi, const __half* __restrict__ Alo,
    const __half* __restrict__ Bhi, const __half* __restrict__ Blo,
    float* __restrict__ Cf, __half* __restrict__ Chi, __half* __restrict__ Clo,
    int lda, int ldb, int ldc,
    long strAb, long strAh, long strBb, long strBh, long strCb, long strCh,
    int Kd, float alpha,
    const float* __restrict__ sb1g, const float* __restrict__ sw2g,
    const float* __restrict__ sb2g)
{
    constexpr int NPL = (NPROD == 3) ? 4 : (NPROD == 2 ? 3 : 2);
    constexpr int STG = NPL * PLANE_B;
    extern __shared__ char smem[];
    const uint32_t smb = smem_u32(smem);
    const int tid  = threadIdx.x;
    const int wid  = tid >> 5;
    const int lane = tid & 31;
    const int wm   = wid & 1;
    const int wn   = wid >> 1;
    const int qrow = lane >> 2;
    const int qk   = (lane & 3) * 2;

    const int z = blockIdx.z, zb = z >> 4, zh = z & 15;
    const long m0 = (long)blockIdx.y * 128;
    const long n0 = (long)blockIdx.x * 128;

    const __half* pg[4];
    int pld[4];
    pg[0] = Ahi + zb * strAb + zh * strAh + m0 * lda;  pld[0] = lda;
    pg[1] = Bhi + zb * strBb + zh * strBh + n0 * ldb;  pld[1] = ldb;
    pg[2] = (NPROD >= 2) ? (Blo + zb * strBb + zh * strBh + n0 * ldb) : pg[1];
    pld[2] = ldb;
    pg[3] = (NPROD == 3) ? (Alo + zb * strAb + zh * strAh + m0 * lda) : pg[0];
    pld[3] = lda;

    const int r0 = tid >> 2, s0 = tid & 3;
    const int r1 = r0 + 64;

    float acc[4][4][4], axx[4][4][4];
#pragma unroll
    for (int i = 0; i < 4; i++)
#pragma unroll
        for (int j = 0; j < 4; j++)
#pragma unroll
            for (int r = 0; r < 4; r++) { acc[i][j][r] = 0.f; axx[i][j][r] = 0.f; }

    const int NC = Kd / 32;

#pragma unroll
    for (int p = 0; p < NPL; p++) {
        cp16(smb + p * PLANE_B + r0 * (SKW * 2) + s0 * 16, pg[p] + (long)r0 * pld[p] + s0 * 8);
        cp16(smb + p * PLANE_B + r1 * (SKW * 2) + s0 * 16, pg[p] + (long)r1 * pld[p] + s0 * 8);
    }
    cp_commit();

    for (int ch = 0; ch < NC; ch++) {
        const int st = ch & 1;
        if (ch + 1 < NC) {
            const int k0 = (ch + 1) * 32;
            const uint32_t sb = smb + (st ^ 1) * STG;
#pragma unroll
            for (int p = 0; p < NPL; p++) {
                cp16(sb + p * PLANE_B + r0 * (SKW * 2) + s0 * 16, pg[p] + (long)r0 * pld[p] + k0 + s0 * 8);
                cp16(sb + p * PLANE_B + r1 * (SKW * 2) + s0 * 16, pg[p] + (long)r1 * pld[p] + k0 + s0 * 8);
            }
            cp_commit();
            cp_wait<1>();
        } else {
            cp_wait<0>();
        }
        __syncthreads();

        const uint32_t* pAh = (const uint32_t*)(smem + st * STG + 0 * PLANE_B);
        const uint32_t* pBh = (const uint32_t*)(smem + st * STG + 1 * PLANE_B);
        const uint32_t* pBl = (const uint32_t*)(smem + st * STG + 2 * PLANE_B);
        const uint32_t* pAl = (const uint32_t*)(smem + st * STG + 3 * PLANE_B);

#pragma unroll
        for (int ks = 0; ks < 2; ks++) {
            const int kb = ks * 16;
            uint32_t af[4][4], bf[4][2];
#pragma unroll
            for (int mt = 0; mt < 4; mt++) {
                const int mr = wm * 64 + mt * 16 + qrow;
                af[mt][0] = pAh[(mr * SKW + kb + qk) >> 1];
                af[mt][1] = pAh[((mr + 8) * SKW + kb + qk) >> 1];
                af[mt][2] = pAh[(mr * SKW + kb + qk + 8) >> 1];
                af[mt][3] = pAh[((mr + 8) * SKW + kb + qk + 8) >> 1];
            }
#pragma unroll
            for (int nt = 0; nt < 4; nt++) {
                const int nr = wn * 32 + nt * 8 + qrow;
                bf[nt][0] = pBh[(nr * SKW + kb + qk) >> 1];
                bf[nt][1] = pBh[(nr * SKW + kb + qk + 8) >> 1];
            }
#pragma unroll
            for (int mt = 0; mt < 4; mt++)
#pragma unroll
                for (int nt = 0; nt < 4; nt++)
                    mma16816(acc[mt][nt], af[mt], bf[nt][0], bf[nt][1]);
            if (NPROD >= 2) {
                uint32_t bl[4][2];
#pragma unroll
                for (int nt = 0; nt < 4; nt++) {
                    const int nr = wn * 32 + nt * 8 + qrow;
                    bl[nt][0] = pBl[(nr * SKW + kb + qk) >> 1];
                    bl[nt][1] = pBl[(nr * SKW + kb + qk + 8) >> 1];
                }
#pragma unroll
                for (int mt = 0; mt < 4; mt++)
#pragma unroll
                    for (int nt = 0; nt < 4; nt++)
                        mma16816(axx[mt][nt], af[mt], bl[nt][0], bl[nt][1]);
            }
            if (NPROD == 3) {
#pragma unroll
                for (int mt = 0; mt < 4; mt++) {
                    const int mr = wm * 64 + mt * 16 + qrow;
                    af[mt][0] = pAl[(mr * SKW + kb + qk) >> 1];
                    af[mt][1] = pAl[((mr + 8) * SKW + kb + qk) >> 1];
                    af[mt][2] = pAl[(mr * SKW + kb + qk + 8) >> 1];
                    af[mt][3] = pAl[((mr + 8) * SKW + kb + qk + 8) >> 1];
                }
#pragma unroll
                for (int mt = 0; mt < 4; mt++)
#pragma unroll
                    for (int nt = 0; nt < 4; nt++)
                        mma16816(axx[mt][nt], af[mt], bf[nt][0], bf[nt][1]);
            }
        }
        __syncthreads();
    }

    // ---- stage fp32 tile in smem ----
    float* cs = (float*)smem;   // [128][132]
    float* sb1s = (float*)(smem + 128 * 132 * 4);          // EMIT==3 extras
    float* sw2s = sb1s + 128;
    const float inv64 = 1.0f / 64.0f;
#pragma unroll
    for (int mt = 0; mt < 4; mt++) {
#pragma unroll
        for (int nt = 0; nt < 4; nt++) {
            const int r = wm * 64 + mt * 16 + qrow;
            const int c = wn * 32 + nt * 8 + (lane & 3) * 2;
            if (NPROD >= 2) {
                cs[r * 132 + c]           = alpha * (acc[mt][nt][0] + axx[mt][nt][0] * inv64);
                cs[r * 132 + c + 1]       = alpha * (acc[mt][nt][1] + axx[mt][nt][1] * inv64);
                cs[(r + 8) * 132 + c]     = alpha * (acc[mt][nt][2] + axx[mt][nt][2] * inv64);
                cs[(r + 8) * 132 + c + 1] = alpha * (acc[mt][nt][3] + axx[mt][nt][3] * inv64);
            } else {
                cs[r * 132 + c]           = alpha * acc[mt][nt][0];
                cs[r * 132 + c + 1]       = alpha * acc[mt][nt][1];
                cs[(r + 8) * 132 + c]     = alpha * acc[mt][nt][2];
                cs[(r + 8) * 132 + c + 1] = alpha * acc[mt][nt][3];
            }
        }
    }
    if (EMIT == 3) {
        if (tid < 128) sb1s[tid] = sb1g[tid];
        else           sw2s[tid - 128] = sw2g[tid - 128];
    }
    __syncthreads();

    const int row = tid >> 1;
    const int hf  = tid & 1;
    if (EMIT == 3) {
        const float* crow = cs + row * 132 + hf * 64;
        float s = 0.f;
#pragma unroll
        for (int i = 0; i < 64; i++)
            s += fmaxf(crow[i] + sb1s[hf * 64 + i], 0.f) * sw2s[hf * 64 + i];
        s += __shfl_xor_sync(0xFFFFFFFFu, s, 1);
        if (hf == 0)
            Cf[zb * strCb + zh * strCh + m0 + row] = s + sb2g[0];
    } else if (EMIT == 4) {
        float* crow = cs + row * 132 + hf * 64;
        float m = -1e30f;
#pragma unroll
        for (int i = 0; i < 64; i++) m = fmaxf(m, crow[i]);
        m = fmaxf(m, __shfl_xor_sync(0xFFFFFFFFu, m, 1));
        float sum = 0.f;
#pragma unroll
        for (int i = 0; i < 64; i++) {
            float e = expf(crow[i] - m);
            crow[i] = e;
            sum += e;
        }
        sum += __shfl_xor_sync(0xFFFFFFFFu, sum, 1);
        const float inv = 1.0f / sum;
        __half2* ph = (__half2*)(Chi + zb * strCb + zh * strCh + (m0 + row) * (long)ldc + hf * 64);
#pragma unroll
        for (int i = 0; i < 16; i++) {
            float4 v = ((const float4*)crow)[i];
            ph[2 * i]     = __halves2half2(__float2half_rn(v.x * inv), __float2half_rn(v.y * inv));
            ph[2 * i + 1] = __halves2half2(__float2half_rn(v.z * inv), __float2half_rn(v.w * inv));
        }
    } else {
        const float4* srow = (const float4*)(cs + row * 132 + hf * 64);
        const long cbase = zb * strCb + zh * strCh + (m0 + row) * (long)ldc + n0 + hf * 64;
        if (EMIT == 0) {
            float4* crow = (float4*)(Cf + cbase);
#pragma unroll
            for (int i = 0; i < 16; i++) crow[i] = srow[i];
        } else {
            __half2* hrow = (__half2*)(Chi + cbase);
            __half2* lrow = (EMIT == 1) ? (__half2*)(Clo + cbase) : nullptr;
#pragma unroll
            for (int i = 0; i < 16; i++) {
                float4 v = srow[i];
                __half hx = __float2half_rn(v.x), hy = __float2half_rn(v.y);
                __half hz = __float2half_rn(v.z), hw = __float2half_rn(v.w);
                hrow[2 * i]     = __halves2half2(hx, hy);
                hrow[2 * i + 1] = __halves2half2(hz, hw);
                if (EMIT == 1) {
                    __half lx = __float2half_rn((v.x - __half2float(hx)) * 64.f);
                    __half ly = __float2half_rn((v.y - __half2float(hy)) * 64.f);
                    __half lz = __float2half_rn((v.z - __half2float(hz)) * 64.f);
                    __half lw = __float2half_rn((v.w - __half2float(hw)) * 64.f);
                    lrow[2 * i]     = __halves2half2(lx, ly);
                    lrow[2 * i + 1] = __halves2half2(lz, lw);
                }
            }
        }
    }
}

// =================== WIDE 1-prod HMMA GEMM (128x256 tile): C = A * B^T =====
#define STGW (PLANE_B + PLANE_BW)    // 30720 per stage

template<int EMIT>
__global__ __launch_bounds__(256, 1) void hgemm_w(
    const __half* __restrict__ Ahi, const __half* __restrict__ Bhi,
    float* __restrict__ Cf, __half* __restrict__ Chi, __half* __restrict__ Clo,
    int lda, int ldb, int ldc, int Kd)
{
    extern __shared__ char smem[];
    const uint32_t smb = smem_u32(smem);
    const int tid  = threadIdx.x;
    const int wid  = tid >> 5;
    const int lane = tid & 31;
    const int wm   = wid & 1;
    const int wn   = wid >> 1;
    const int qrow = lane >> 2;
    const int qk   = (lane & 3) * 2;

    const long m0 = (long)blockIdx.y * 128;
    const long n0 = (long)blockIdx.x * 256;

    const __half* gA = Ahi + m0 * lda;
    const __half* gB = Bhi + n0 * ldb;

    const int r0 = tid >> 2, s0 = tid & 3;

    float acc[4][8][4];
#pragma unroll
    for (int i = 0; i < 4; i++)
#pragma unroll
        for (int j = 0; j < 8; j++)
#pragma unroll
            for (int r = 0; r < 4; r++) acc[i][j][r] = 0.f;

    const int NC = Kd / 32;

    cp16(smb + r0 * (SKW * 2) + s0 * 16, gA + (long)r0 * lda + s0 * 8);
    cp16(smb + (r0 + 64) * (SKW * 2) + s0 * 16, gA + (long)(r0 + 64) * lda + s0 * 8);
#pragma unroll
    for (int q = 0; q < 4; q++)
        cp16(smb + PLANE_B + (r0 + q * 64) * (SKW * 2) + s0 * 16,
             gB + (long)(r0 + q * 64) * ldb + s0 * 8);
    cp_commit();

    for (int ch = 0; ch < NC; ch++) {
        const int st = ch & 1;
        if (ch + 1 < NC) {
            const int k0 = (ch + 1) * 32;
            const uint32_t sb = smb + (st ^ 1) * STGW;
            cp16(sb + r0 * (SKW * 2) + s0 * 16, gA + (long)r0 * lda + k0 + s0 * 8);
            cp16(sb + (r0 + 64) * (SKW * 2) + s0 * 16, gA + (long)(r0 + 64) * lda + k0 + s0 * 8);
#pragma unroll
            for (int q = 0; q < 4; q++)
                cp16(sb + PLANE_B + (r0 + q * 64) * (SKW * 2) + s0 * 16,
                     gB + (long)(r0 + q * 64) * ldb + k0 + s0 * 8);
            cp_commit();
            cp_wait<1>();
        } else {
            cp_wait<0>();
        }
        __syncthreads();

        const uint32_t* pA = (const uint32_t*)(smem + st * STGW);
        const uint32_t* pB = (const uint32_t*)(smem + st * STGW + PLANE_B);

#pragma unroll
        for (int ks = 0; ks < 2; ks++) {
            const int kb = ks * 16;
            uint32_t af[4][4], bf[8][2];
#pragma unroll
            for (int mt = 0; mt < 4; mt++) {
                const int mr = wm * 64 + mt * 16 + qrow;
                af[mt][0] = pA[(mr * SKW + kb + qk) >> 1];
                af[mt][1] = pA[((mr + 8) * SKW + kb + qk) >> 1];
                af[mt][2] = pA[(mr * SKW + kb + qk + 8) >> 1];
                af[mt][3] = pA[((mr + 8) * SKW + kb + qk + 8) >> 1];
            }
#pragma unroll
            for (int nt = 0; nt < 8; nt++) {
                const int nr = wn * 64 + nt * 8 + qrow;
                bf[nt][0] = pB[(nr * SKW + kb + qk) >> 1];
                bf[nt][1] = pB[(nr * SKW + kb + qk + 8) >> 1];
            }
#pragma unroll
            for (int mt = 0; mt < 4; mt++)
#pragma unroll
                for (int nt = 0; nt < 8; nt++)
                    mma16816(acc[mt][nt], af[mt], bf[nt][0], bf[nt][1]);
        }
        __syncthreads();
    }

    float* cs = (float*)smem;
#pragma unroll
    for (int mt = 0; mt < 4; mt++) {
#pragma unroll
        for (int nt = 0; nt < 8; nt++) {
            const int r = wm * 64 + mt * 16 + qrow;
            const int c = wn * 64 + nt * 8 + (lane & 3) * 2;
            cs[r * 260 + c]           = acc[mt][nt][0];
            cs[r * 260 + c + 1]       = acc[mt][nt][1];
            cs[(r + 8) * 260 + c]     = acc[mt][nt][2];
            cs[(r + 8) * 260 + c + 1] = acc[mt][nt][3];
        }
    }
    __syncthreads();
    {
        const int row = tid >> 1;
        const int hf  = tid & 1;
        const float4* srow = (const float4*)(cs + row * 260 + hf * 128);
        const long cbase = (m0 + row) * (long)ldc + n0 + hf * 128;
        if (EMIT == 0) {
            float4* crow = (float4*)(Cf + cbase);
#pragma unroll
            for (int i = 0; i < 32; i++) crow[i] = srow[i];
        } else {
            __half2* hrow = (__half2*)(Chi + cbase);
            __half2* lrow = (EMIT == 1) ? (__half2*)(Clo + cbase) : nullptr;
#pragma unroll
            for (int i = 0; i < 32; i++) {
                float4 v = srow[i];
                __half hx = __float2half_rn(v.x), hy = __float2half_rn(v.y);
                __half hz = __float2half_rn(v.z), hw = __float2half_rn(v.w);
                hrow[2 * i]     = __halves2half2(hx, hy);
                hrow[2 * i + 1] = __halves2half2(hz, hw);
                if (EMIT == 1) {
                    __half lx = __float2half_rn((v.x - __half2float(hx)) * 64.f);
                    __half ly = __float2half_rn((v.y - __half2float(hy)) * 64.f);
                    __half lz = __float2half_rn((v.z - __half2float(hz)) * 64.f);
                    __half lw = __float2half_rn((v.w - __half2float(hw)) * 64.f);
                    lrow[2 * i]     = __halves2half2(lx, ly);
                    lrow[2 * i + 1] = __halves2half2(lz, lw);
                }
            }
        }
    }
}

// ---------------- sparsek projection + exact top-128 ----------------
__device__ __forceinline__ unsigned enc_desc(float v) {
    unsigned b = __float_as_uint(v);
    unsigned o = (b & 0x80000000u) ? ~b : (b | 0x80000000u);
    return ~o;
}
__device__ __forceinline__ float dec_desc(unsigned d) {
    unsigned o = ~d;
    unsigned b = (o & 0x80000000u) ? (o ^ 0x80000000u) : ~o;
    return __uint_as_float(b);
}

__global__ __launch_bounds__(1024) void sparsek_topk(const float* __restrict__ scores,
                                                     int* __restrict__ out_idx)
{
    __shared__ unsigned long long key[SS];
    __shared__ unsigned char flag[SS];
    __shared__ float fred[32];
    __shared__ int   ired[32];
    __shared__ int   rho_s, npos_s;
    __shared__ float tau_s;
    int bh  = blockIdx.x;
    int tid = threadIdx.x;
    int lane = tid & 31, warp = tid >> 5;
    const float* s = scores + (long)bh * SS;

    for (int i = tid; i < SS; i += 1024)
        key[i] = ((unsigned long long)enc_desc(s[i]) << 32) | (unsigned)i;
    __syncthreads();

    for (int k = 2; k <= SS; k <<= 1) {
        for (int j = k >> 1; j > 0; j >>= 1) {
            for (int i = tid; i < SS; i += 1024) {
                int ixj = i ^ j;
                if (ixj > i) {
                    bool up = ((i & k) == 0);
                    unsigned long long a = key[i], b = key[ixj];
                    if ((a > b) == up) { key[i] = b; key[ixj] = a; }
                }
            }
            __syncthreads();
        }
    }

    float v[4], pc[4];
#pragma unroll
    for (int j = 0; j < 4; j++) v[j] = dec_desc((unsigned)(key[tid * 4 + j] >> 32));
    pc[0] = v[0]; pc[1] = pc[0] + v[1]; pc[2] = pc[1] + v[2]; pc[3] = pc[2] + v[3];
    float tot = pc[3];
#pragma unroll
    for (int o = 1; o < 32; o <<= 1) {
        float n = __shfl_up_sync(0xFFFFFFFFu, tot, o);
        if (lane >= o) tot += n;
    }
    if (lane == 31) fred[warp] = tot;
    __syncthreads();
    if (warp == 0) {
        float w = fred[lane];
#pragma unroll
        for (int o = 1; o < 32; o <<= 1) {
            float n = __shfl_up_sync(0xFFFFFFFFu, w, o);
            if (lane >= o) w += n;
        }
        fred[lane] = w;
    }
    __syncthreads();
    const float base = (warp ? fred[warp - 1] : 0.f) + (tot - pc[3]);

    int cnt = 0;
#pragma unroll
    for (int j = 0; j < 4; j++) {
        float csj = base + pc[j];
        float thr = (csj - (float)KSEL) / (float)(tid * 4 + j + 1);
        if (v[j] > thr) cnt++;
    }
#pragma unroll
    for (int o = 16; o > 0; o >>= 1) cnt += __shfl_xor_sync(0xFFFFFFFFu, cnt, o);
    if (lane == 0) ired[warp] = cnt;
    __syncthreads();
    if (tid == 0) {
        int r = 0;
#pragma unroll
        for (int i = 0; i < 32; i++) r += ired[i];
        rho_s = (r < 1) ? 1 : r;
    }
    __syncthreads();
    const int rho = rho_s;
    {
        int rr = rho - 1;
        if ((rr >> 2) == tid)
            tau_s = (base + pc[rr & 3] - (float)KSEL) / (float)rho;
    }
    __syncthreads();
    const float tau = tau_s;
    int cnp = 0;
#pragma unroll
    for (int j = 0; j < 4; j++) if (v[j] > tau) cnp++;
#pragma unroll
    for (int o = 16; o > 0; o >>= 1) cnp += __shfl_xor_sync(0xFFFFFFFFu, cnp, o);
    if (lane == 0) ired[warp] = cnp;
    __syncthreads();
    if (tid == 0) {
        int r = 0;
#pragma unroll
        for (int i = 0; i < 32; i++) r += ired[i];
        npos_s = r;
    }
    __syncthreads();

    const int npos = npos_s;
    if (npos >= KSEL) {
        if (tid < KSEL)
            out_idx[bh * KSEL + tid] = (int)(key[tid] & 0xFFFFFFFFu);
    } else {
        if (tid < npos)
            out_idx[bh * KSEL + tid] = (int)(key[tid] & 0xFFFFFFFFu);
        for (int i = tid; i < SS; i += 1024) flag[i] = 0;
        __syncthreads();
        for (int i = tid; i < npos; i += 1024)
            flag[key[i] & 0xFFFFFFFFu] = 1;
        __syncthreads();
        if (tid == 0) {
            int c2 = npos;
            for (int i = 0; i < SS && c2 < KSEL; i++)
                if (!flag[i]) out_idx[bh * KSEL + c2++] = i;
        }
    }
}

// ---------------- gather selected K (hi+lo) and X rows (hi) ----------------
__global__ void gather_kx(const __half* __restrict__ Khi, const __half* __restrict__ Klo,
                          const __half* __restrict__ Xhi,
                          const int* __restrict__ idx,
                          __half* __restrict__ kh, __half* __restrict__ kl,
                          __half* __restrict__ xsel)
{
    int bh = blockIdx.x >> 7;
    int j  = blockIdx.x & 127;
    int t  = threadIdx.x;        // 0..255
    int b  = bh >> 4, h = bh & 15;
    int row = idx[bh * KSEL + j];
    long src = ((long)(b * SS + row)) * HH;
    const uint4* xs = (const uint4*)(Xhi + src);
    uint4* xd = (uint4*)(xsel + (long)bh * (KSEL * HH) + (long)j * HH);
    xd[t] = xs[t];
    if (t < 16) {
        const uint4* ks = (const uint4*)(Khi + src + h * HDIM);
        uint4* kd = (uint4*)(kh + (long)bh * (KSEL * HDIM) + (long)j * HDIM);
        kd[t] = ks[t];
    } else if (t < 32) {
        int tt = t - 16;
        const uint4* ks = (const uint4*)(Klo + src + h * HDIM);
        uint4* kd = (uint4*)(kl + (long)bh * (KSEL * HDIM) + (long)j * HDIM);
        kd[tt] = ks[tt];
    }
}

// ---------------- launch ----------------
extern "C" void kernel_launch(void* const* d_in, const int* in_sizes, int n_in,
                              void* d_out, int out_size)
{
    const float* x   = (const float*)d_in[0];
    const float* wq  = (const float*)d_in[1];
    const float* wk  = (const float*)d_in[2];
    const float* wv  = (const float*)d_in[3];
    const float* wo  = (const float*)d_in[4];
    const float* sw1 = (const float*)d_in[5];
    const float* sb1 = (const float*)d_in[6];
    const float* sw2 = (const float*)d_in[7];
    const float* sb2 = (const float*)d_in[8];
    float* out = (float*)d_out;

    float *pScores;
    int* pIdx;
    __half *pXhi, *pXlo, *pQhi, *pKhi, *pKlo, *pPhi, *pOhi, *pXsel;
    __half *pWq, *pWkhi, *pWklo, *pWv, *pWo, *pSw1hi, *pSw1lo;
    __half *pKselh, *pKsell, *pVselTh, *pVselTl;
    cudaGetSymbolAddress((void**)&pScores, gScores);
    cudaGetSymbolAddress((void**)&pIdx,    gIdx);
    cudaGetSymbolAddress((void**)&pXhi,    gXhi);
    cudaGetSymbolAddress((void**)&pXlo,    gXlo);
    cudaGetSymbolAddress((void**)&pQhi,    gQhi);
    cudaGetSymbolAddress((void**)&pKhi,    gKhi);
    cudaGetSymbolAddress((void**)&pKlo,    gKlo);
    cudaGetSymbolAddress((void**)&pPhi,    gPhi);
    cudaGetSymbolAddress((void**)&pOhi,    gOhi);
    cudaGetSymbolAddress((void**)&pWq,     gWq);
    cudaGetSymbolAddress((void**)&pWkhi,   gWkhi);
    cudaGetSymbolAddress((void**)&pWklo,   gWklo);
    cudaGetSymbolAddress((void**)&pWv,     gWv);
    cudaGetSymbolAddress((void**)&pWo,     gWo);
    cudaGetSymbolAddress((void**)&pSw1hi,  gSw1hi);
    cudaGetSymbolAddress((void**)&pSw1lo,  gSw1lo);
    cudaGetSymbolAddress((void**)&pXsel,   gXsel);
    cudaGetSymbolAddress((void**)&pKselh,  gKselh);
    cudaGetSymbolAddress((void**)&pKsell,  gKsell);
    cudaGetSymbolAddress((void**)&pVselTh, gVselTh);
    cudaGetSymbolAddress((void**)&pVselTl, gVselTl);

    const int SM1 = 67584;    // max(2*2*10240, 128*132*4)
    const int SM2 = 67584;
    const int SM3 = 81920;    // 2*4*10240  (covers cs + sb1/sw2 stash: 68608)
    const int SMW = 133120;   // max(2*30720, 128*260*4)
    cudaFuncSetAttribute(hgemm_w<0>, cudaFuncAttributeMaxDynamicSharedMemorySize, SMW);
    cudaFuncSetAttribute(hgemm_w<2>, cudaFuncAttributeMaxDynamicSharedMemorySize, SMW);
    cudaFuncSetAttribute(hgemm<1,1>, cudaFuncAttributeMaxDynamicSharedMemorySize, SM1);
    cudaFuncSetAttribute(hgemm<2,2>, cudaFuncAttributeMaxDynamicSharedMemorySize, SM2);
    cudaFuncSetAttribute(hgemm<2,4>, cudaFuncAttributeMaxDynamicSharedMemorySize, SM2);
    cudaFuncSetAttribute(hgemm<3,1>, cudaFuncAttributeMaxDynamicSharedMemorySize, SM3);
    cudaFuncSetAttribute(hgemm<3,3>, cudaFuncAttributeMaxDynamicSharedMemorySize, SM3);

    const long sBH  = (long)SS * HH;
    const long sHd  = HDIM;
    const long sTb  = (long)NHEADS * SS * HDIM;
    const long sTh  = (long)SS * HDIM;
    const long sSelb = (long)KSEL * HDIM * NHEADS;
    const long sSelh = (long)KSEL * HDIM;
    const long sXsb  = (long)NHEADS * KSEL * HH;
    const long sXsh  = (long)KSEL * HH;
    const long sScb  = (long)NHEADS * SS;
    const long sSch  = (long)SS;

    dim3 gProj(HH / 128, NROWS / 128, 1);   // (16, 64, 1) narrow
    dim3 gProjW(HH / 256, NROWS / 128, 1);  // (8, 64, 1) wide
    dim3 gAtt(1, SS / 128, NBH);            // (1, 32, 32)
    dim3 gVsel(1, 1, NBH);                  // (1, 1, 32)

    // ---- split X (hi+lo, vectorized) + ALL weights in one launch ----
    splitX<<<(int)((ROWHID / 8 + 255) / 256), 256>>>(x, pXhi, pXlo, ROWHID / 8);
    splitW<<<(int)((WN / 8 + 255) / 256), 256>>>(wq, wk, wv, wo, sw1,
                                                 pWq, pWkhi, pWklo, pWv, pWo,
                                                 pSw1hi, pSw1lo);

    // ---- Q = X @ wq^T (1-prod wide, emit hi only) ----
    hgemm_w<2><<<gProjW, 256, SMW>>>(pXhi, pWq, nullptr, pQhi, nullptr, HH, HH, HH, HH);
    // ---- K = X @ wk^T (3-prod, protects selection; emit hi+lo) ----
    hgemm<3,1><<<gProj, 256, SM3>>>(pXhi, pXlo, pWkhi, pWklo, nullptr, pKhi, pKlo,
                                    HH, HH, HH, 0, 0, 0, 0, 0, 0, HH, 1.0f,
                                    nullptr, nullptr, nullptr);

    // ---- kv_scores: hidden GEMM (3-prod) fused with relu-dot score head ----
    hgemm<3,3><<<gAtt, 256, SM3>>>(pKhi, pKlo, pSw1hi, pSw1lo, pScores, nullptr, nullptr,
                                   HH, HDIM, 1,
                                   sBH, sHd, 0, 0, sScb, sSch, HDIM, 1.0f,
                                   sb1, sw2, sb2);
    sparsek_topk<<<NBH, 1024>>>(pScores, pIdx);
    gather_kx<<<NBH * KSEL, 256>>>(pKhi, pKlo, pXhi, pIdx, pKselh, pKsell, pXsel);

    // ---- VselT = wv_head_hi @ Xsel_hi^T (1-prod batched, emit hi+lo) ----
    hgemm<1,1><<<gVsel, 256, SM1>>>(pWv, nullptr, pXsel, nullptr,
                                    nullptr, pVselTh, pVselTl,
                                    HH, HH, KSEL,
                                    0, (long)HDIM * HH,
                                    sXsb, sXsh,
                                    (long)NHEADS * KSEL * HDIM, sSelh,
                                    HH, 1.0f, nullptr, nullptr, nullptr);

    // ---- P = softmax(Q_head @ Ksel^T * scale)  (2-prod, fused softmax, fp16) ----
    const float scale = 0.08838834764831845f;
    hgemm<2,4><<<gAtt, 256, SM2>>>(pQhi, nullptr, pKselh, pKsell, nullptr, pPhi, nullptr,
                                   HH, HDIM, HDIM,
                                   sBH, sHd, sSelb, sSelh, sTb, sTh, HDIM, scale,
                                   nullptr, nullptr, nullptr);

    // ---- out_head = P @ Vsel (2-prod batched, emit hi), [B,S,H] layout ----
    hgemm<2,2><<<gAtt, 256, SM2>>>(pPhi, nullptr, pVselTh, pVselTl, nullptr, pOhi, nullptr,
                                   HDIM, KSEL, HH,
                                   sTb, sTh, sSelb, sSelh, sBH, sHd, KSEL, 1.0f,
                                   nullptr, nullptr, nullptr);

    // ---- out = O @ wo^T (1-prod wide, fp32 out) ----
    hgemm_w<0><<<gProjW, 256, SMW>>>(pOhi, pWo, out, nullptr, nullptr, HH, HH, HH, HH);
}